// round 1
// baseline (speedup 1.0000x reference)
#include <cuda_runtime.h>

#define N_NODES 20000
#define N_EDGES 640000
#define HS 256
#define H_HEADS 8
#define DK 32
#define FF_DIM 1024
#define N_LAYERS 2

// ---------------- scratch (static device globals; no runtime alloc) ----------------
__device__ float g_q[(size_t)N_NODES * HS];
__device__ float g_k[(size_t)N_NODES * HS];
__device__ float g_v[(size_t)N_NODES * HS];
__device__ float g_o[(size_t)N_NODES * HS];
__device__ float g_tmp[(size_t)N_NODES * HS];
__device__ float g_h[(size_t)N_NODES * HS];
__device__ float g_xbuf[(size_t)N_NODES * HS];
__device__ float g_ff[(size_t)N_NODES * FF_DIM];

__device__ int g_cnt[N_NODES];
__device__ int g_rowptr[N_NODES + 1];
__device__ int g_cursor[N_NODES];
__device__ int g_eids[N_EDGES];

// ---------------- CSR build ----------------
__global__ void zero_cnt_kernel() {
    int i = blockIdx.x * blockDim.x + threadIdx.x;
    if (i < N_NODES) g_cnt[i] = 0;
}

__global__ void hist_kernel(const int* __restrict__ dst) {
    int i = blockIdx.x * blockDim.x + threadIdx.x;
    if (i < N_EDGES) atomicAdd(&g_cnt[dst[i]], 1);
}

// single-block Hillis-Steele scan over N_NODES counts
__global__ void scan_kernel() {
    __shared__ int sh[1024];
    __shared__ int carry_sh;
    if (threadIdx.x == 0) carry_sh = 0;
    __syncthreads();
    for (int base = 0; base < N_NODES; base += 1024) {
        int i = base + threadIdx.x;
        int v = (i < N_NODES) ? g_cnt[i] : 0;
        sh[threadIdx.x] = v;
        __syncthreads();
        #pragma unroll
        for (int off = 1; off < 1024; off <<= 1) {
            int t = (threadIdx.x >= off) ? sh[threadIdx.x - off] : 0;
            __syncthreads();
            sh[threadIdx.x] += t;
            __syncthreads();
        }
        int incl = sh[threadIdx.x];
        int excl = incl - v + carry_sh;
        if (i < N_NODES) {
            g_rowptr[i] = excl;
            g_cursor[i] = excl;
        }
        __syncthreads();
        if (threadIdx.x == 1023) carry_sh += sh[1023];
        __syncthreads();
    }
    if (threadIdx.x == 0) g_rowptr[N_NODES] = carry_sh;
}

__global__ void scatter_kernel(const int* __restrict__ dst) {
    int i = blockIdx.x * blockDim.x + threadIdx.x;
    if (i < N_EDGES) {
        int p = atomicAdd(&g_cursor[dst[i]], 1);
        g_eids[p] = i;
    }
}

// ---------------- SGEMM: C = epilogue(A[MxK] @ B[KxN] + bias [+ res]) ----------------
// MODE 0: +bias (bias may be null)
// MODE 1: relu(+bias)
// MODE 2: +bias +res
#define BM 128
#define BN 128
#define BK 8
#define TM 8
#define TN 8

template <int MODE>
__global__ __launch_bounds__(256, 2) void sgemm_kernel(
    int M, int K, int Nc,
    const float* __restrict__ A,
    const float* __restrict__ B,
    const float* __restrict__ bias,
    const float* __restrict__ res,
    float* __restrict__ C)
{
    __shared__ float As[BK][BM];
    __shared__ float Bs[BK][BN];
    int tid = threadIdx.x;
    int m0 = blockIdx.y * BM;
    int n0 = blockIdx.x * BN;

    int a_row = tid >> 1;           // 0..127
    int a_col = (tid & 1) * 4;      // 0 or 4
    int b_row = tid >> 5;           // 0..7
    int b_col = (tid & 31) * 4;     // 0..124

    int ty = tid >> 4;              // 0..15
    int tx = tid & 15;              // 0..15

    float acc[TM][TN];
    #pragma unroll
    for (int i = 0; i < TM; i++)
        #pragma unroll
        for (int j = 0; j < TN; j++) acc[i][j] = 0.f;

    for (int k0 = 0; k0 < K; k0 += BK) {
        float4 av = make_float4(0.f, 0.f, 0.f, 0.f);
        if (m0 + a_row < M)
            av = *(const float4*)(A + (size_t)(m0 + a_row) * K + k0 + a_col);
        As[a_col + 0][a_row] = av.x;
        As[a_col + 1][a_row] = av.y;
        As[a_col + 2][a_row] = av.z;
        As[a_col + 3][a_row] = av.w;
        float4 bv = *(const float4*)(B + (size_t)(k0 + b_row) * Nc + n0 + b_col);
        *(float4*)(&Bs[b_row][b_col]) = bv;
        __syncthreads();

        #pragma unroll
        for (int kk = 0; kk < BK; kk++) {
            float4 rm0 = *(const float4*)(&As[kk][ty * TM]);
            float4 rm1 = *(const float4*)(&As[kk][ty * TM + 4]);
            float4 rn0 = *(const float4*)(&Bs[kk][tx * TN]);
            float4 rn1 = *(const float4*)(&Bs[kk][tx * TN + 4]);
            float rm[TM] = {rm0.x, rm0.y, rm0.z, rm0.w, rm1.x, rm1.y, rm1.z, rm1.w};
            float rn[TN] = {rn0.x, rn0.y, rn0.z, rn0.w, rn1.x, rn1.y, rn1.z, rn1.w};
            #pragma unroll
            for (int i = 0; i < TM; i++)
                #pragma unroll
                for (int j = 0; j < TN; j++)
                    acc[i][j] += rm[i] * rn[j];
        }
        __syncthreads();
    }

    #pragma unroll
    for (int i = 0; i < TM; i++) {
        int m = m0 + ty * TM + i;
        if (m >= M) continue;
        #pragma unroll
        for (int j = 0; j < TN; j += 4) {
            int n = n0 + tx * TN + j;
            float4 v = make_float4(acc[i][j], acc[i][j + 1], acc[i][j + 2], acc[i][j + 3]);
            if (bias) {
                const float4 bb = *(const float4*)(bias + n);
                v.x += bb.x; v.y += bb.y; v.z += bb.z; v.w += bb.w;
            }
            if (MODE == 2) {
                const float4 rr = *(const float4*)(res + (size_t)m * Nc + n);
                v.x += rr.x; v.y += rr.y; v.z += rr.z; v.w += rr.w;
            }
            if (MODE == 1) {
                v.x = fmaxf(v.x, 0.f); v.y = fmaxf(v.y, 0.f);
                v.z = fmaxf(v.z, 0.f); v.w = fmaxf(v.w, 0.f);
            }
            *(float4*)(C + (size_t)m * Nc + n) = v;
        }
    }
}

// ---------------- edge aggregation: one warp per destination node ----------------
__global__ void edge_agg_kernel(const float* __restrict__ rel,
                                const int* __restrict__ edge_feat,
                                const int* __restrict__ src)
{
    int gw = (blockIdx.x * blockDim.x + threadIdx.x) >> 5;
    int lane = threadIdx.x & 31;
    if (gw >= N_NODES) return;

    const float4* qr = (const float4*)(g_q + (size_t)gw * HS);
    float4 q0 = qr[2 * lane], q1 = qr[2 * lane + 1];

    float4 a0 = make_float4(0.f, 0.f, 0.f, 0.f);
    float4 a1 = make_float4(0.f, 0.f, 0.f, 0.f);
    float zsum = 0.f;

    int beg = g_rowptr[gw], end = g_rowptr[gw + 1];
    int ecol = 2 * (lane & 3);  // float4 index within the DK=32 rel row
    const float invs = 0.17677669529663687f;  // 1/sqrt(32)

    for (int j = beg; j < end; j++) {
        int e = g_eids[j];
        int s = src[e];
        int r = edge_feat[e];
        const float4* kr = (const float4*)(g_k + (size_t)s * HS);
        const float4* vr = (const float4*)(g_v + (size_t)s * HS);
        const float4* er = (const float4*)(rel + (size_t)r * DK);
        float4 k0 = kr[2 * lane], k1 = kr[2 * lane + 1];
        float4 e0 = er[ecol], e1 = er[ecol + 1];

        float d = (k0.x + e0.x) * q0.x + (k0.y + e0.y) * q0.y
                + (k0.z + e0.z) * q0.z + (k0.w + e0.w) * q0.w
                + (k1.x + e1.x) * q1.x + (k1.y + e1.y) * q1.y
                + (k1.z + e1.z) * q1.z + (k1.w + e1.w) * q1.w;
        d += __shfl_xor_sync(0xffffffffu, d, 1);
        d += __shfl_xor_sync(0xffffffffu, d, 2);
        float sc = __expf(fminf(fmaxf(d * invs, -10.f), 10.f));

        float4 v0 = vr[2 * lane], v1 = vr[2 * lane + 1];
        a0.x += (v0.x + e0.x) * sc; a0.y += (v0.y + e0.y) * sc;
        a0.z += (v0.z + e0.z) * sc; a0.w += (v0.w + e0.w) * sc;
        a1.x += (v1.x + e1.x) * sc; a1.y += (v1.y + e1.y) * sc;
        a1.z += (v1.z + e1.z) * sc; a1.w += (v1.w + e1.w) * sc;
        zsum += sc;
    }

    float inv = 1.f / zsum;
    float4* orow = (float4*)(g_o + (size_t)gw * HS);
    orow[2 * lane]     = make_float4(a0.x * inv, a0.y * inv, a0.z * inv, a0.w * inv);
    orow[2 * lane + 1] = make_float4(a1.x * inv, a1.y * inv, a1.z * inv, a1.w * inv);
}

// ---------------- layernorm: one warp per row ----------------
__global__ void ln_kernel(const float* __restrict__ in,
                          const float* __restrict__ gamma,
                          const float* __restrict__ beta,
                          float* __restrict__ out)
{
    int gw = (blockIdx.x * blockDim.x + threadIdx.x) >> 5;
    int lane = threadIdx.x & 31;
    if (gw >= N_NODES) return;

    const float4* row = (const float4*)(in + (size_t)gw * HS);
    float4 x0 = row[2 * lane], x1 = row[2 * lane + 1];

    float s = x0.x + x0.y + x0.z + x0.w + x1.x + x1.y + x1.z + x1.w;
    #pragma unroll
    for (int off = 16; off; off >>= 1) s += __shfl_xor_sync(0xffffffffu, s, off);
    float mean = s * (1.f / HS);

    float d0 = x0.x - mean, d1 = x0.y - mean, d2 = x0.z - mean, d3 = x0.w - mean;
    float d4 = x1.x - mean, d5 = x1.y - mean, d6 = x1.z - mean, d7 = x1.w - mean;
    float ss = d0 * d0 + d1 * d1 + d2 * d2 + d3 * d3 + d4 * d4 + d5 * d5 + d6 * d6 + d7 * d7;
    #pragma unroll
    for (int off = 16; off; off >>= 1) ss += __shfl_xor_sync(0xffffffffu, ss, off);
    float rstd = rsqrtf(ss * (1.f / HS) + 1e-5f);

    const float4* gr = (const float4*)gamma;
    const float4* br = (const float4*)beta;
    float4 gg0 = gr[2 * lane], gg1 = gr[2 * lane + 1];
    float4 bb0 = br[2 * lane], bb1 = br[2 * lane + 1];

    float4* orow = (float4*)(out + (size_t)gw * HS);
    orow[2 * lane] = make_float4(d0 * rstd * gg0.x + bb0.x, d1 * rstd * gg0.y + bb0.y,
                                 d2 * rstd * gg0.z + bb0.z, d3 * rstd * gg0.w + bb0.w);
    orow[2 * lane + 1] = make_float4(d4 * rstd * gg1.x + bb0.x * 0.f + bb1.x,
                                     d5 * rstd * gg1.y + bb1.y,
                                     d6 * rstd * gg1.z + bb1.z,
                                     d7 * rstd * gg1.w + bb1.w);
}

// ---------------- host orchestration ----------------
extern "C" void kernel_launch(void* const* d_in, const int* in_sizes, int n_in,
                              void* d_out, int out_size)
{
    const float* x_in     = (const float*)d_in[0];
    const int*   edge_feat= (const int*)  d_in[1];
    const int*   src      = (const int*)  d_in[2];
    const int*   dst      = (const int*)  d_in[3];
    const float* rel      = (const float*)d_in[4];
    const float* Wq       = (const float*)d_in[5];
    const float* bq       = (const float*)d_in[6];
    const float* Wk       = (const float*)d_in[7];
    const float* Wv       = (const float*)d_in[8];
    const float* Wo       = (const float*)d_in[9];
    const float* bo       = (const float*)d_in[10];
    const float* W1       = (const float*)d_in[11];
    const float* b1       = (const float*)d_in[12];
    const float* W2       = (const float*)d_in[13];
    const float* b2       = (const float*)d_in[14];
    const float* ln1g     = (const float*)d_in[15];
    const float* ln1b     = (const float*)d_in[16];
    const float* ln2g     = (const float*)d_in[17];
    const float* ln2b     = (const float*)d_in[18];

    float *q, *k, *v, *o, *tmp, *h, *xbuf, *ff;
    cudaGetSymbolAddress((void**)&q,    g_q);
    cudaGetSymbolAddress((void**)&k,    g_k);
    cudaGetSymbolAddress((void**)&v,    g_v);
    cudaGetSymbolAddress((void**)&o,    g_o);
    cudaGetSymbolAddress((void**)&tmp,  g_tmp);
    cudaGetSymbolAddress((void**)&h,    g_h);
    cudaGetSymbolAddress((void**)&xbuf, g_xbuf);
    cudaGetSymbolAddress((void**)&ff,   g_ff);

    // CSR by dst (same for both layers)
    zero_cnt_kernel<<<(N_NODES + 255) / 256, 256>>>();
    hist_kernel<<<(N_EDGES + 255) / 256, 256>>>(dst);
    scan_kernel<<<1, 1024>>>();
    scatter_kernel<<<(N_EDGES + 255) / 256, 256>>>(dst);

    const int warp_blocks = (N_NODES * 32 + 255) / 256;
    dim3 gHS(HS / BN, (N_NODES + BM - 1) / BM);
    dim3 gFF(FF_DIM / BN, (N_NODES + BM - 1) / BM);

    const float* xin = x_in;
    for (int l = 0; l < N_LAYERS; l++) {
        const float* wq = Wq + (size_t)l * HS * HS;
        const float* wk = Wk + (size_t)l * HS * HS;
        const float* wv = Wv + (size_t)l * HS * HS;
        const float* wo = Wo + (size_t)l * HS * HS;
        const float* w1 = W1 + (size_t)l * HS * FF_DIM;
        const float* w2 = W2 + (size_t)l * FF_DIM * HS;

        sgemm_kernel<0><<<gHS, 256>>>(N_NODES, HS, HS, xin, wq, bq + l * HS, nullptr, q);
        sgemm_kernel<0><<<gHS, 256>>>(N_NODES, HS, HS, xin, wk, nullptr, nullptr, k);
        sgemm_kernel<0><<<gHS, 256>>>(N_NODES, HS, HS, xin, wv, nullptr, nullptr, v);

        edge_agg_kernel<<<warp_blocks, 256>>>(rel, edge_feat, src);

        sgemm_kernel<2><<<gHS, 256>>>(N_NODES, HS, HS, o, wo, bo + l * HS, xin, tmp);
        ln_kernel<<<warp_blocks, 256>>>(tmp, ln1g + l * HS, ln1b + l * HS, h);

        sgemm_kernel<1><<<gFF, 256>>>(N_NODES, HS, FF_DIM, h, w1, b1 + l * FF_DIM, nullptr, ff);
        sgemm_kernel<2><<<gHS, 256>>>(N_NODES, FF_DIM, HS, ff, w2, b2 + l * HS, h, tmp);

        float* xnext = (l == N_LAYERS - 1) ? (float*)d_out : xbuf;
        ln_kernel<<<warp_blocks, 256>>>(tmp, ln2g + l * HS, ln2b + l * HS, xnext);
        xin = xbuf;
    }
}

// round 2
// speedup vs baseline: 2.3141x; 2.3141x over previous
#include <cuda_runtime.h>
#include <cstdint>

#define N_NODES 20000
#define N_EDGES 640000
#define HS 256
#define H_HEADS 8
#define DK 32
#define FF_DIM 1024
#define N_LAYERS 2

// ---------------- scratch (static device globals; no runtime alloc) ----------------
__device__ float g_q[(size_t)N_NODES * HS];
__device__ float g_k[(size_t)N_NODES * HS];
__device__ float g_v[(size_t)N_NODES * HS];
__device__ float g_o[(size_t)N_NODES * HS];
__device__ float g_tmp[(size_t)N_NODES * HS];
__device__ float g_h[(size_t)N_NODES * HS];
__device__ float g_xbuf[(size_t)N_NODES * HS];
__device__ float g_ff[(size_t)N_NODES * FF_DIM];

__device__ int g_cnt[N_NODES];
__device__ int g_rowptr[N_NODES + 1];
__device__ int g_cursor[N_NODES];
__device__ int g_eids[N_EDGES];

// ---------------- CSR build ----------------
__global__ void zero_cnt_kernel() {
    int i = blockIdx.x * blockDim.x + threadIdx.x;
    if (i < N_NODES) g_cnt[i] = 0;
}

__global__ void hist_kernel(const int* __restrict__ dst) {
    int i = blockIdx.x * blockDim.x + threadIdx.x;
    if (i < N_EDGES) atomicAdd(&g_cnt[dst[i]], 1);
}

__global__ void scan_kernel() {
    __shared__ int sh[1024];
    __shared__ int carry_sh;
    if (threadIdx.x == 0) carry_sh = 0;
    __syncthreads();
    for (int base = 0; base < N_NODES; base += 1024) {
        int i = base + threadIdx.x;
        int v = (i < N_NODES) ? g_cnt[i] : 0;
        sh[threadIdx.x] = v;
        __syncthreads();
        #pragma unroll
        for (int off = 1; off < 1024; off <<= 1) {
            int t = (threadIdx.x >= off) ? sh[threadIdx.x - off] : 0;
            __syncthreads();
            sh[threadIdx.x] += t;
            __syncthreads();
        }
        int incl = sh[threadIdx.x];
        int excl = incl - v + carry_sh;
        if (i < N_NODES) {
            g_rowptr[i] = excl;
            g_cursor[i] = excl;
        }
        __syncthreads();
        if (threadIdx.x == 1023) carry_sh += sh[1023];
        __syncthreads();
    }
    if (threadIdx.x == 0) g_rowptr[N_NODES] = carry_sh;
}

__global__ void scatter_kernel(const int* __restrict__ dst) {
    int i = blockIdx.x * blockDim.x + threadIdx.x;
    if (i < N_EDGES) {
        int p = atomicAdd(&g_cursor[dst[i]], 1);
        g_eids[p] = i;
    }
}

// ---------------- TF32 tensor-core GEMM ----------------
// C[M,Nc] = epi(A[M,K] @ B[K,Nc] + bias [+ res])
// MODE 0: +bias (nullable)   MODE 1: relu(+bias)   MODE 2: +bias +res
#define BM 128
#define BN 128
#define BK 16
#define SPAD 8
#define SSTRIDE (BM + SPAD)   // 136; bank = (8*k + m) % 32 -> conflict-free frags

__device__ __forceinline__ uint32_t f2tf32(float f) {
    uint32_t u;
    asm("cvt.rna.tf32.f32 %0, %1;" : "=r"(u) : "f"(f));
    return u;
}

__device__ __forceinline__ void mma_tf32(float4& c, const uint32_t a[4], const uint32_t b[2]) {
    asm volatile(
        "mma.sync.aligned.m16n8k8.row.col.f32.tf32.tf32.f32 "
        "{%0,%1,%2,%3}, {%4,%5,%6,%7}, {%8,%9}, {%0,%1,%2,%3};"
        : "+f"(c.x), "+f"(c.y), "+f"(c.z), "+f"(c.w)
        : "r"(a[0]), "r"(a[1]), "r"(a[2]), "r"(a[3]), "r"(b[0]), "r"(b[1]));
}

template <int MODE>
__global__ __launch_bounds__(256, 2) void tf32_gemm_kernel(
    int M, int K, int Nc,
    const float* __restrict__ A,
    const float* __restrict__ B,
    const float* __restrict__ bias,
    const float* __restrict__ res,
    float* __restrict__ C)
{
    __shared__ uint32_t As[2][BK][SSTRIDE];   // [k][m]
    __shared__ uint32_t Bs[2][BK][SSTRIDE];   // [k][n]

    const int tid  = threadIdx.x;
    const int lane = tid & 31;
    const int warp = tid >> 5;
    const int g = lane >> 2;     // 0..7
    const int q = lane & 3;      // 0..3
    const int wm = (warp >> 2) * 64;   // 0 / 64
    const int wn = (warp & 3) * 32;    // 0 / 32 / 64 / 96

    const int m0 = blockIdx.y * BM;
    const int n0 = blockIdx.x * BN;

    float4 acc[4][4];
    #pragma unroll
    for (int i = 0; i < 4; i++)
        #pragma unroll
        for (int j = 0; j < 4; j++) acc[i][j] = make_float4(0.f, 0.f, 0.f, 0.f);

    // global-load mapping (per BK=16 chunk): 512 float4 for each tile, 2 per thread
    // A: idx -> row=idx/4, kc=idx%4 ; B: idx -> krow=idx/32, nc=idx%32
    const int a_row0 = tid >> 2;          // idx=tid      (i=0)
    const int a_kc0  = (tid & 3) * 4;
    const int a_row1 = (tid + 256) >> 2;  // i=1
    const int a_kc1  = a_kc0;             // (tid+256)%4 == tid%4
    const int b_k0   = tid >> 5;
    const int b_n0   = (tid & 31) * 4;
    const int b_k1   = (tid + 256) >> 5;
    const int b_n1   = b_n0;

    const int nch = K >> 4;

    float4 aR[2], bR[2];

    // prime chunk 0
    {
        aR[0] = make_float4(0.f, 0.f, 0.f, 0.f);
        aR[1] = make_float4(0.f, 0.f, 0.f, 0.f);
        if (m0 + a_row0 < M) aR[0] = *(const float4*)(A + (size_t)(m0 + a_row0) * K + a_kc0);
        if (m0 + a_row1 < M) aR[1] = *(const float4*)(A + (size_t)(m0 + a_row1) * K + a_kc1);
        bR[0] = *(const float4*)(B + (size_t)b_k0 * Nc + n0 + b_n0);
        bR[1] = *(const float4*)(B + (size_t)b_k1 * Nc + n0 + b_n1);

        As[0][a_kc0 + 0][a_row0] = f2tf32(aR[0].x);
        As[0][a_kc0 + 1][a_row0] = f2tf32(aR[0].y);
        As[0][a_kc0 + 2][a_row0] = f2tf32(aR[0].z);
        As[0][a_kc0 + 3][a_row0] = f2tf32(aR[0].w);
        As[0][a_kc1 + 0][a_row1] = f2tf32(aR[1].x);
        As[0][a_kc1 + 1][a_row1] = f2tf32(aR[1].y);
        As[0][a_kc1 + 2][a_row1] = f2tf32(aR[1].z);
        As[0][a_kc1 + 3][a_row1] = f2tf32(aR[1].w);
        {
            uint4 u0 = make_uint4(f2tf32(bR[0].x), f2tf32(bR[0].y), f2tf32(bR[0].z), f2tf32(bR[0].w));
            uint4 u1 = make_uint4(f2tf32(bR[1].x), f2tf32(bR[1].y), f2tf32(bR[1].z), f2tf32(bR[1].w));
            *(uint4*)(&Bs[0][b_k0][b_n0]) = u0;
            *(uint4*)(&Bs[0][b_k1][b_n1]) = u1;
        }
    }
    __syncthreads();

    for (int ch = 0; ch < nch; ch++) {
        const int cur = ch & 1;
        const int nxt = cur ^ 1;
        const bool has_next = (ch + 1 < nch);

        if (has_next) {
            const int k0 = (ch + 1) * BK;
            aR[0] = make_float4(0.f, 0.f, 0.f, 0.f);
            aR[1] = make_float4(0.f, 0.f, 0.f, 0.f);
            if (m0 + a_row0 < M) aR[0] = *(const float4*)(A + (size_t)(m0 + a_row0) * K + k0 + a_kc0);
            if (m0 + a_row1 < M) aR[1] = *(const float4*)(A + (size_t)(m0 + a_row1) * K + k0 + a_kc1);
            bR[0] = *(const float4*)(B + (size_t)(k0 + b_k0) * Nc + n0 + b_n0);
            bR[1] = *(const float4*)(B + (size_t)(k0 + b_k1) * Nc + n0 + b_n1);
        }

        // compute 2 k-steps of 8
        #pragma unroll
        for (int ks = 0; ks < BK; ks += 8) {
            uint32_t afr[4][4];
            uint32_t bfr[4][2];
            #pragma unroll
            for (int mt = 0; mt < 4; mt++) {
                const int m = wm + mt * 16 + g;
                afr[mt][0] = As[cur][ks + q][m];
                afr[mt][1] = As[cur][ks + q][m + 8];
                afr[mt][2] = As[cur][ks + q + 4][m];
                afr[mt][3] = As[cur][ks + q + 4][m + 8];
            }
            #pragma unroll
            for (int nt = 0; nt < 4; nt++) {
                const int n = wn + nt * 8 + g;
                bfr[nt][0] = Bs[cur][ks + q][n];
                bfr[nt][1] = Bs[cur][ks + q + 4][n];
            }
            #pragma unroll
            for (int mt = 0; mt < 4; mt++)
                #pragma unroll
                for (int nt = 0; nt < 4; nt++)
                    mma_tf32(acc[mt][nt], afr[mt], bfr[nt]);
        }

        if (has_next) {
            As[nxt][a_kc0 + 0][a_row0] = f2tf32(aR[0].x);
            As[nxt][a_kc0 + 1][a_row0] = f2tf32(aR[0].y);
            As[nxt][a_kc0 + 2][a_row0] = f2tf32(aR[0].z);
            As[nxt][a_kc0 + 3][a_row0] = f2tf32(aR[0].w);
            As[nxt][a_kc1 + 0][a_row1] = f2tf32(aR[1].x);
            As[nxt][a_kc1 + 1][a_row1] = f2tf32(aR[1].y);
            As[nxt][a_kc1 + 2][a_row1] = f2tf32(aR[1].z);
            As[nxt][a_kc1 + 3][a_row1] = f2tf32(aR[1].w);
            uint4 u0 = make_uint4(f2tf32(bR[0].x), f2tf32(bR[0].y), f2tf32(bR[0].z), f2tf32(bR[0].w));
            uint4 u1 = make_uint4(f2tf32(bR[1].x), f2tf32(bR[1].y), f2tf32(bR[1].z), f2tf32(bR[1].w));
            *(uint4*)(&Bs[nxt][b_k0][b_n0]) = u0;
            *(uint4*)(&Bs[nxt][b_k1][b_n1]) = u1;
            __syncthreads();
        }
    }

    // epilogue
    #pragma unroll
    for (int mt = 0; mt < 4; mt++) {
        #pragma unroll
        for (int nt = 0; nt < 4; nt++) {
            const int row0 = m0 + wm + mt * 16 + g;
            const int row1 = row0 + 8;
            const int col  = n0 + wn + nt * 8 + q * 2;
            float2 v0 = make_float2(acc[mt][nt].x, acc[mt][nt].y);
            float2 v1 = make_float2(acc[mt][nt].z, acc[mt][nt].w);
            if (bias) {
                float2 bb = *(const float2*)(bias + col);
                v0.x += bb.x; v0.y += bb.y;
                v1.x += bb.x; v1.y += bb.y;
            }
            if (MODE == 2) {
                if (row0 < M) {
                    float2 r0 = *(const float2*)(res + (size_t)row0 * Nc + col);
                    v0.x += r0.x; v0.y += r0.y;
                }
                if (row1 < M) {
                    float2 r1 = *(const float2*)(res + (size_t)row1 * Nc + col);
                    v1.x += r1.x; v1.y += r1.y;
                }
            }
            if (MODE == 1) {
                v0.x = fmaxf(v0.x, 0.f); v0.y = fmaxf(v0.y, 0.f);
                v1.x = fmaxf(v1.x, 0.f); v1.y = fmaxf(v1.y, 0.f);
            }
            if (row0 < M) *(float2*)(C + (size_t)row0 * Nc + col) = v0;
            if (row1 < M) *(float2*)(C + (size_t)row1 * Nc + col) = v1;
        }
    }
}

// ---------------- edge aggregation: one warp per destination node ----------------
__global__ void edge_agg_kernel(const float* __restrict__ rel,
                                const int* __restrict__ edge_feat,
                                const int* __restrict__ src)
{
    int gw = (blockIdx.x * blockDim.x + threadIdx.x) >> 5;
    int lane = threadIdx.x & 31;
    if (gw >= N_NODES) return;

    const float4* qr = (const float4*)(g_q + (size_t)gw * HS);
    float4 q0 = qr[2 * lane], q1 = qr[2 * lane + 1];

    float4 a0 = make_float4(0.f, 0.f, 0.f, 0.f);
    float4 a1 = make_float4(0.f, 0.f, 0.f, 0.f);
    float zsum = 0.f;

    int beg = g_rowptr[gw], end = g_rowptr[gw + 1];
    int ecol = 2 * (lane & 3);
    const float invs = 0.17677669529663687f;

    for (int j = beg; j < end; j++) {
        int e = g_eids[j];
        int s = src[e];
        int r = edge_feat[e];
        const float4* kr = (const float4*)(g_k + (size_t)s * HS);
        const float4* vr = (const float4*)(g_v + (size_t)s * HS);
        const float4* er = (const float4*)(rel + (size_t)r * DK);
        float4 k0 = kr[2 * lane], k1 = kr[2 * lane + 1];
        float4 e0 = er[ecol], e1 = er[ecol + 1];

        float d = (k0.x + e0.x) * q0.x + (k0.y + e0.y) * q0.y
                + (k0.z + e0.z) * q0.z + (k0.w + e0.w) * q0.w
                + (k1.x + e1.x) * q1.x + (k1.y + e1.y) * q1.y
                + (k1.z + e1.z) * q1.z + (k1.w + e1.w) * q1.w;
        d += __shfl_xor_sync(0xffffffffu, d, 1);
        d += __shfl_xor_sync(0xffffffffu, d, 2);
        float sc = __expf(fminf(fmaxf(d * invs, -10.f), 10.f));

        float4 v0 = vr[2 * lane], v1 = vr[2 * lane + 1];
        a0.x += (v0.x + e0.x) * sc; a0.y += (v0.y + e0.y) * sc;
        a0.z += (v0.z + e0.z) * sc; a0.w += (v0.w + e0.w) * sc;
        a1.x += (v1.x + e1.x) * sc; a1.y += (v1.y + e1.y) * sc;
        a1.z += (v1.z + e1.z) * sc; a1.w += (v1.w + e1.w) * sc;
        zsum += sc;
    }

    float inv = 1.f / zsum;
    float4* orow = (float4*)(g_o + (size_t)gw * HS);
    orow[2 * lane]     = make_float4(a0.x * inv, a0.y * inv, a0.z * inv, a0.w * inv);
    orow[2 * lane + 1] = make_float4(a1.x * inv, a1.y * inv, a1.z * inv, a1.w * inv);
}

// ---------------- layernorm: one warp per row ----------------
__global__ void ln_kernel(const float* __restrict__ in,
                          const float* __restrict__ gamma,
                          const float* __restrict__ beta,
                          float* __restrict__ out)
{
    int gw = (blockIdx.x * blockDim.x + threadIdx.x) >> 5;
    int lane = threadIdx.x & 31;
    if (gw >= N_NODES) return;

    const float4* row = (const float4*)(in + (size_t)gw * HS);
    float4 x0 = row[2 * lane], x1 = row[2 * lane + 1];

    float s = x0.x + x0.y + x0.z + x0.w + x1.x + x1.y + x1.z + x1.w;
    #pragma unroll
    for (int off = 16; off; off >>= 1) s += __shfl_xor_sync(0xffffffffu, s, off);
    float mean = s * (1.f / HS);

    float d0 = x0.x - mean, d1 = x0.y - mean, d2 = x0.z - mean, d3 = x0.w - mean;
    float d4 = x1.x - mean, d5 = x1.y - mean, d6 = x1.z - mean, d7 = x1.w - mean;
    float ss = d0 * d0 + d1 * d1 + d2 * d2 + d3 * d3 + d4 * d4 + d5 * d5 + d6 * d6 + d7 * d7;
    #pragma unroll
    for (int off = 16; off; off >>= 1) ss += __shfl_xor_sync(0xffffffffu, ss, off);
    float rstd = rsqrtf(ss * (1.f / HS) + 1e-5f);

    const float4* gr = (const float4*)gamma;
    const float4* br = (const float4*)beta;
    float4 gg0 = gr[2 * lane], gg1 = gr[2 * lane + 1];
    float4 bb0 = br[2 * lane], bb1 = br[2 * lane + 1];

    float4* orow = (float4*)(out + (size_t)gw * HS);
    orow[2 * lane] = make_float4(d0 * rstd * gg0.x + bb0.x, d1 * rstd * gg0.y + bb0.y,
                                 d2 * rstd * gg0.z + bb0.z, d3 * rstd * gg0.w + bb0.w);
    orow[2 * lane + 1] = make_float4(d4 * rstd * gg1.x + bb1.x,
                                     d5 * rstd * gg1.y + bb1.y,
                                     d6 * rstd * gg1.z + bb1.z,
                                     d7 * rstd * gg1.w + bb1.w);
}

// ---------------- host orchestration ----------------
extern "C" void kernel_launch(void* const* d_in, const int* in_sizes, int n_in,
                              void* d_out, int out_size)
{
    const float* x_in     = (const float*)d_in[0];
    const int*   edge_feat= (const int*)  d_in[1];
    const int*   src      = (const int*)  d_in[2];
    const int*   dst      = (const int*)  d_in[3];
    const float* rel      = (const float*)d_in[4];
    const float* Wq       = (const float*)d_in[5];
    const float* bq       = (const float*)d_in[6];
    const float* Wk       = (const float*)d_in[7];
    const float* Wv       = (const float*)d_in[8];
    const float* Wo       = (const float*)d_in[9];
    const float* bo       = (const float*)d_in[10];
    const float* W1       = (const float*)d_in[11];
    const float* b1       = (const float*)d_in[12];
    const float* W2       = (const float*)d_in[13];
    const float* b2       = (const float*)d_in[14];
    const float* ln1g     = (const float*)d_in[15];
    const float* ln1b     = (const float*)d_in[16];
    const float* ln2g     = (const float*)d_in[17];
    const float* ln2b     = (const float*)d_in[18];

    float *q, *k, *v, *o, *tmp, *h, *xbuf, *ff;
    cudaGetSymbolAddress((void**)&q,    g_q);
    cudaGetSymbolAddress((void**)&k,    g_k);
    cudaGetSymbolAddress((void**)&v,    g_v);
    cudaGetSymbolAddress((void**)&o,    g_o);
    cudaGetSymbolAddress((void**)&tmp,  g_tmp);
    cudaGetSymbolAddress((void**)&h,    g_h);
    cudaGetSymbolAddress((void**)&xbuf, g_xbuf);
    cudaGetSymbolAddress((void**)&ff,   g_ff);

    zero_cnt_kernel<<<(N_NODES + 255) / 256, 256>>>();
    hist_kernel<<<(N_EDGES + 255) / 256, 256>>>(dst);
    scan_kernel<<<1, 1024>>>();
    scatter_kernel<<<(N_EDGES + 255) / 256, 256>>>(dst);

    const int warp_blocks = (N_NODES * 32 + 255) / 256;
    dim3 gHS(HS / BN, (N_NODES + BM - 1) / BM);
    dim3 gFF(FF_DIM / BN, (N_NODES + BM - 1) / BM);

    const float* xin = x_in;
    for (int l = 0; l < N_LAYERS; l++) {
        const float* wq = Wq + (size_t)l * HS * HS;
        const float* wk = Wk + (size_t)l * HS * HS;
        const float* wv = Wv + (size_t)l * HS * HS;
        const float* wo = Wo + (size_t)l * HS * HS;
        const float* w1 = W1 + (size_t)l * HS * FF_DIM;
        const float* w2 = W2 + (size_t)l * FF_DIM * HS;

        tf32_gemm_kernel<0><<<gHS, 256>>>(N_NODES, HS, HS, xin, wq, bq + l * HS, nullptr, q);
        tf32_gemm_kernel<0><<<gHS, 256>>>(N_NODES, HS, HS, xin, wk, nullptr, nullptr, k);
        tf32_gemm_kernel<0><<<gHS, 256>>>(N_NODES, HS, HS, xin, wv, nullptr, nullptr, v);

        edge_agg_kernel<<<warp_blocks, 256>>>(rel, edge_feat, src);

        tf32_gemm_kernel<2><<<gHS, 256>>>(N_NODES, HS, HS, o, wo, bo + l * HS, xin, tmp);
        ln_kernel<<<warp_blocks, 256>>>(tmp, ln1g + l * HS, ln1b + l * HS, h);

        tf32_gemm_kernel<1><<<gFF, 256>>>(N_NODES, HS, FF_DIM, h, w1, b1 + l * FF_DIM, nullptr, ff);
        tf32_gemm_kernel<2><<<gHS, 256>>>(N_NODES, FF_DIM, HS, ff, w2, b2 + l * HS, h, tmp);

        float* xnext = (l == N_LAYERS - 1) ? (float*)d_out : xbuf;
        ln_kernel<<<warp_blocks, 256>>>(tmp, ln2g + l * HS, ln2b + l * HS, xnext);
        xin = xbuf;
    }
}

// round 3
// speedup vs baseline: 2.3198x; 1.0025x over previous
#include <cuda_runtime.h>
#include <cstdint>

#define N_NODES 20000
#define N_EDGES 640000
#define HS 256
#define H_HEADS 8
#define DK 32
#define FF_DIM 1024
#define N_LAYERS 2

// ---------------- scratch (static device globals; no runtime alloc) ----------------
__device__ float g_q[(size_t)N_NODES * HS];
__device__ float g_k[(size_t)N_NODES * HS];
__device__ float g_v[(size_t)N_NODES * HS];
__device__ float g_o[(size_t)N_NODES * HS];
__device__ float g_tmp[(size_t)N_NODES * HS];
__device__ float g_h[(size_t)N_NODES * HS];
__device__ float g_xbuf[(size_t)N_NODES * HS];
__device__ float g_ff[(size_t)N_NODES * FF_DIM];

__device__ int g_cnt[N_NODES];
__device__ int g_rowptr[N_NODES + 1];
__device__ int g_cursor[N_NODES];
__device__ int g_eids[N_EDGES];

// ---------------- CSR build ----------------
__global__ void zero_cnt_kernel() {
    int i = blockIdx.x * blockDim.x + threadIdx.x;
    if (i < N_NODES) g_cnt[i] = 0;
}

__global__ void hist_kernel(const int* __restrict__ dst) {
    int i = blockIdx.x * blockDim.x + threadIdx.x;
    if (i < N_EDGES) atomicAdd(&g_cnt[dst[i]], 1);
}

__global__ void scan_kernel() {
    __shared__ int sh[1024];
    __shared__ int carry_sh;
    if (threadIdx.x == 0) carry_sh = 0;
    __syncthreads();
    for (int base = 0; base < N_NODES; base += 1024) {
        int i = base + threadIdx.x;
        int v = (i < N_NODES) ? g_cnt[i] : 0;
        sh[threadIdx.x] = v;
        __syncthreads();
        #pragma unroll
        for (int off = 1; off < 1024; off <<= 1) {
            int t = (threadIdx.x >= off) ? sh[threadIdx.x - off] : 0;
            __syncthreads();
            sh[threadIdx.x] += t;
            __syncthreads();
        }
        int incl = sh[threadIdx.x];
        int excl = incl - v + carry_sh;
        if (i < N_NODES) {
            g_rowptr[i] = excl;
            g_cursor[i] = excl;
        }
        __syncthreads();
        if (threadIdx.x == 1023) carry_sh += sh[1023];
        __syncthreads();
    }
    if (threadIdx.x == 0) g_rowptr[N_NODES] = carry_sh;
}

__global__ void scatter_kernel(const int* __restrict__ dst) {
    int i = blockIdx.x * blockDim.x + threadIdx.x;
    if (i < N_EDGES) {
        int p = atomicAdd(&g_cursor[dst[i]], 1);
        g_eids[p] = i;
    }
}

// ---------------- TF32 tensor-core GEMM ----------------
// C[M,Nc] = epi(A[M,K] @ B[K,Nc] + bias [+ res])
// MODE 0: +bias (nullable)   MODE 1: relu(+bias)   MODE 2: +bias +res
#define BM 128
#define BN 128
#define BK 16
#define SPAD 8
#define SSTRIDE (BM + SPAD)   // 136; bank = (8*k + m) % 32 -> conflict-free frags

__device__ __forceinline__ uint32_t f2tf32(float f) {
    uint32_t u;
    asm("cvt.rna.tf32.f32 %0, %1;" : "=r"(u) : "f"(f));
    return u;
}

__device__ __forceinline__ void mma_tf32(float4& c, const uint32_t a[4], const uint32_t b[2]) {
    asm volatile(
        "mma.sync.aligned.m16n8k8.row.col.f32.tf32.tf32.f32 "
        "{%0,%1,%2,%3}, {%4,%5,%6,%7}, {%8,%9}, {%0,%1,%2,%3};"
        : "+f"(c.x), "+f"(c.y), "+f"(c.z), "+f"(c.w)
        : "r"(a[0]), "r"(a[1]), "r"(a[2]), "r"(a[3]), "r"(b[0]), "r"(b[1]));
}

template <int MODE>
__global__ __launch_bounds__(256, 2) void tf32_gemm_kernel(
    int M, int K, int Nc,
    const float* __restrict__ A,
    const float* __restrict__ B,
    const float* __restrict__ bias,
    const float* __restrict__ res,
    float* __restrict__ C)
{
    __shared__ uint32_t As[2][BK][SSTRIDE];   // [k][m]
    __shared__ uint32_t Bs[2][BK][SSTRIDE];   // [k][n]

    const int tid  = threadIdx.x;
    const int lane = tid & 31;
    const int warp = tid >> 5;
    const int g = lane >> 2;     // 0..7
    const int q = lane & 3;      // 0..3
    const int wm = (warp >> 2) * 64;   // 0 / 64
    const int wn = (warp & 3) * 32;    // 0 / 32 / 64 / 96

    const int m0 = blockIdx.y * BM;
    const int n0 = blockIdx.x * BN;

    float4 acc[4][4];
    #pragma unroll
    for (int i = 0; i < 4; i++)
        #pragma unroll
        for (int j = 0; j < 4; j++) acc[i][j] = make_float4(0.f, 0.f, 0.f, 0.f);

    // global-load mapping (per BK=16 chunk): 512 float4 for each tile, 2 per thread
    // A: idx -> row=idx/4, kc=idx%4 ; B: idx -> krow=idx/32, nc=idx%32
    const int a_row0 = tid >> 2;          // idx=tid      (i=0)
    const int a_kc0  = (tid & 3) * 4;
    const int a_row1 = (tid + 256) >> 2;  // i=1
    const int a_kc1  = a_kc0;             // (tid+256)%4 == tid%4
    const int b_k0   = tid >> 5;
    const int b_n0   = (tid & 31) * 4;
    const int b_k1   = (tid + 256) >> 5;
    const int b_n1   = b_n0;

    const int nch = K >> 4;

    float4 aR[2], bR[2];

    // prime chunk 0
    {
        aR[0] = make_float4(0.f, 0.f, 0.f, 0.f);
        aR[1] = make_float4(0.f, 0.f, 0.f, 0.f);
        if (m0 + a_row0 < M) aR[0] = *(const float4*)(A + (size_t)(m0 + a_row0) * K + a_kc0);
        if (m0 + a_row1 < M) aR[1] = *(const float4*)(A + (size_t)(m0 + a_row1) * K + a_kc1);
        bR[0] = *(const float4*)(B + (size_t)b_k0 * Nc + n0 + b_n0);
        bR[1] = *(const float4*)(B + (size_t)b_k1 * Nc + n0 + b_n1);

        As[0][a_kc0 + 0][a_row0] = f2tf32(aR[0].x);
        As[0][a_kc0 + 1][a_row0] = f2tf32(aR[0].y);
        As[0][a_kc0 + 2][a_row0] = f2tf32(aR[0].z);
        As[0][a_kc0 + 3][a_row0] = f2tf32(aR[0].w);
        As[0][a_kc1 + 0][a_row1] = f2tf32(aR[1].x);
        As[0][a_kc1 + 1][a_row1] = f2tf32(aR[1].y);
        As[0][a_kc1 + 2][a_row1] = f2tf32(aR[1].z);
        As[0][a_kc1 + 3][a_row1] = f2tf32(aR[1].w);
        {
            uint4 u0 = make_uint4(f2tf32(bR[0].x), f2tf32(bR[0].y), f2tf32(bR[0].z), f2tf32(bR[0].w));
            uint4 u1 = make_uint4(f2tf32(bR[1].x), f2tf32(bR[1].y), f2tf32(bR[1].z), f2tf32(bR[1].w));
            *(uint4*)(&Bs[0][b_k0][b_n0]) = u0;
            *(uint4*)(&Bs[0][b_k1][b_n1]) = u1;
        }
    }
    __syncthreads();

    for (int ch = 0; ch < nch; ch++) {
        const int cur = ch & 1;
        const int nxt = cur ^ 1;
        const bool has_next = (ch + 1 < nch);

        if (has_next) {
            const int k0 = (ch + 1) * BK;
            aR[0] = make_float4(0.f, 0.f, 0.f, 0.f);
            aR[1] = make_float4(0.f, 0.f, 0.f, 0.f);
            if (m0 + a_row0 < M) aR[0] = *(const float4*)(A + (size_t)(m0 + a_row0) * K + k0 + a_kc0);
            if (m0 + a_row1 < M) aR[1] = *(const float4*)(A + (size_t)(m0 + a_row1) * K + k0 + a_kc1);
            bR[0] = *(const float4*)(B + (size_t)(k0 + b_k0) * Nc + n0 + b_n0);
            bR[1] = *(const float4*)(B + (size_t)(k0 + b_k1) * Nc + n0 + b_n1);
        }

        // compute 2 k-steps of 8
        #pragma unroll
        for (int ks = 0; ks < BK; ks += 8) {
            uint32_t afr[4][4];
            uint32_t bfr[4][2];
            #pragma unroll
            for (int mt = 0; mt < 4; mt++) {
                const int m = wm + mt * 16 + g;
                afr[mt][0] = As[cur][ks + q][m];
                afr[mt][1] = As[cur][ks + q][m + 8];
                afr[mt][2] = As[cur][ks + q + 4][m];
                afr[mt][3] = As[cur][ks + q + 4][m + 8];
            }
            #pragma unroll
            for (int nt = 0; nt < 4; nt++) {
                const int n = wn + nt * 8 + g;
                bfr[nt][0] = Bs[cur][ks + q][n];
                bfr[nt][1] = Bs[cur][ks + q + 4][n];
            }
            #pragma unroll
            for (int mt = 0; mt < 4; mt++)
                #pragma unroll
                for (int nt = 0; nt < 4; nt++)
                    mma_tf32(acc[mt][nt], afr[mt], bfr[nt]);
        }

        if (has_next) {
            As[nxt][a_kc0 + 0][a_row0] = f2tf32(aR[0].x);
            As[nxt][a_kc0 + 1][a_row0] = f2tf32(aR[0].y);
            As[nxt][a_kc0 + 2][a_row0] = f2tf32(aR[0].z);
            As[nxt][a_kc0 + 3][a_row0] = f2tf32(aR[0].w);
            As[nxt][a_kc1 + 0][a_row1] = f2tf32(aR[1].x);
            As[nxt][a_kc1 + 1][a_row1] = f2tf32(aR[1].y);
            As[nxt][a_kc1 + 2][a_row1] = f2tf32(aR[1].z);
            As[nxt][a_kc1 + 3][a_row1] = f2tf32(aR[1].w);
            uint4 u0 = make_uint4(f2tf32(bR[0].x), f2tf32(bR[0].y), f2tf32(bR[0].z), f2tf32(bR[0].w));
            uint4 u1 = make_uint4(f2tf32(bR[1].x), f2tf32(bR[1].y), f2tf32(bR[1].z), f2tf32(bR[1].w));
            *(uint4*)(&Bs[nxt][b_k0][b_n0]) = u0;
            *(uint4*)(&Bs[nxt][b_k1][b_n1]) = u1;
            __syncthreads();
        }
    }

    // epilogue
    #pragma unroll
    for (int mt = 0; mt < 4; mt++) {
        #pragma unroll
        for (int nt = 0; nt < 4; nt++) {
            const int row0 = m0 + wm + mt * 16 + g;
            const int row1 = row0 + 8;
            const int col  = n0 + wn + nt * 8 + q * 2;
            float2 v0 = make_float2(acc[mt][nt].x, acc[mt][nt].y);
            float2 v1 = make_float2(acc[mt][nt].z, acc[mt][nt].w);
            if (bias) {
                float2 bb = *(const float2*)(bias + col);
                v0.x += bb.x; v0.y += bb.y;
                v1.x += bb.x; v1.y += bb.y;
            }
            if (MODE == 2) {
                if (row0 < M) {
                    float2 r0 = *(const float2*)(res + (size_t)row0 * Nc + col);
                    v0.x += r0.x; v0.y += r0.y;
                }
                if (row1 < M) {
                    float2 r1 = *(const float2*)(res + (size_t)row1 * Nc + col);
                    v1.x += r1.x; v1.y += r1.y;
                }
            }
            if (MODE == 1) {
                v0.x = fmaxf(v0.x, 0.f); v0.y = fmaxf(v0.y, 0.f);
                v1.x = fmaxf(v1.x, 0.f); v1.y = fmaxf(v1.y, 0.f);
            }
            if (row0 < M) *(float2*)(C + (size_t)row0 * Nc + col) = v0;
            if (row1 < M) *(float2*)(C + (size_t)row1 * Nc + col) = v1;
        }
    }
}

// ---------------- edge aggregation: one warp per destination node ----------------
__global__ void edge_agg_kernel(const float* __restrict__ rel,
                                const int* __restrict__ edge_feat,
                                const int* __restrict__ src)
{
    int gw = (blockIdx.x * blockDim.x + threadIdx.x) >> 5;
    int lane = threadIdx.x & 31;
    if (gw >= N_NODES) return;

    const float4* qr = (const float4*)(g_q + (size_t)gw * HS);
    float4 q0 = qr[2 * lane], q1 = qr[2 * lane + 1];

    float4 a0 = make_float4(0.f, 0.f, 0.f, 0.f);
    float4 a1 = make_float4(0.f, 0.f, 0.f, 0.f);
    float zsum = 0.f;

    int beg = g_rowptr[gw], end = g_rowptr[gw + 1];
    int ecol = 2 * (lane & 3);
    const float invs = 0.17677669529663687f;

    for (int j = beg; j < end; j++) {
        int e = g_eids[j];
        int s = src[e];
        int r = edge_feat[e];
        const float4* kr = (const float4*)(g_k + (size_t)s * HS);
        const float4* vr = (const float4*)(g_v + (size_t)s * HS);
        const float4* er = (const float4*)(rel + (size_t)r * DK);
        float4 k0 = kr[2 * lane], k1 = kr[2 * lane + 1];
        float4 e0 = er[ecol], e1 = er[ecol + 1];

        float d = (k0.x + e0.x) * q0.x + (k0.y + e0.y) * q0.y
                + (k0.z + e0.z) * q0.z + (k0.w + e0.w) * q0.w
                + (k1.x + e1.x) * q1.x + (k1.y + e1.y) * q1.y
                + (k1.z + e1.z) * q1.z + (k1.w + e1.w) * q1.w;
        d += __shfl_xor_sync(0xffffffffu, d, 1);
        d += __shfl_xor_sync(0xffffffffu, d, 2);
        float sc = __expf(fminf(fmaxf(d * invs, -10.f), 10.f));

        float4 v0 = vr[2 * lane], v1 = vr[2 * lane + 1];
        a0.x += (v0.x + e0.x) * sc; a0.y += (v0.y + e0.y) * sc;
        a0.z += (v0.z + e0.z) * sc; a0.w += (v0.w + e0.w) * sc;
        a1.x += (v1.x + e1.x) * sc; a1.y += (v1.y + e1.y) * sc;
        a1.z += (v1.z + e1.z) * sc; a1.w += (v1.w + e1.w) * sc;
        zsum += sc;
    }

    float inv = 1.f / zsum;
    float4* orow = (float4*)(g_o + (size_t)gw * HS);
    orow[2 * lane]     = make_float4(a0.x * inv, a0.y * inv, a0.z * inv, a0.w * inv);
    orow[2 * lane + 1] = make_float4(a1.x * inv, a1.y * inv, a1.z * inv, a1.w * inv);
}

// ---------------- layernorm: one warp per row ----------------
__global__ void ln_kernel(const float* __restrict__ in,
                          const float* __restrict__ gamma,
                          const float* __restrict__ beta,
                          float* __restrict__ out)
{
    int gw = (blockIdx.x * blockDim.x + threadIdx.x) >> 5;
    int lane = threadIdx.x & 31;
    if (gw >= N_NODES) return;

    const float4* row = (const float4*)(in + (size_t)gw * HS);
    float4 x0 = row[2 * lane], x1 = row[2 * lane + 1];

    float s = x0.x + x0.y + x0.z + x0.w + x1.x + x1.y + x1.z + x1.w;
    #pragma unroll
    for (int off = 16; off; off >>= 1) s += __shfl_xor_sync(0xffffffffu, s, off);
    float mean = s * (1.f / HS);

    float d0 = x0.x - mean, d1 = x0.y - mean, d2 = x0.z - mean, d3 = x0.w - mean;
    float d4 = x1.x - mean, d5 = x1.y - mean, d6 = x1.z - mean, d7 = x1.w - mean;
    float ss = d0 * d0 + d1 * d1 + d2 * d2 + d3 * d3 + d4 * d4 + d5 * d5 + d6 * d6 + d7 * d7;
    #pragma unroll
    for (int off = 16; off; off >>= 1) ss += __shfl_xor_sync(0xffffffffu, ss, off);
    float rstd = rsqrtf(ss * (1.f / HS) + 1e-5f);

    const float4* gr = (const float4*)gamma;
    const float4* br = (const float4*)beta;
    float4 gg0 = gr[2 * lane], gg1 = gr[2 * lane + 1];
    float4 bb0 = br[2 * lane], bb1 = br[2 * lane + 1];

    float4* orow = (float4*)(out + (size_t)gw * HS);
    orow[2 * lane] = make_float4(d0 * rstd * gg0.x + bb0.x, d1 * rstd * gg0.y + bb0.y,
                                 d2 * rstd * gg0.z + bb0.z, d3 * rstd * gg0.w + bb0.w);
    orow[2 * lane + 1] = make_float4(d4 * rstd * gg1.x + bb1.x,
                                     d5 * rstd * gg1.y + bb1.y,
                                     d6 * rstd * gg1.z + bb1.z,
                                     d7 * rstd * gg1.w + bb1.w);
}

// ---------------- host orchestration ----------------
extern "C" void kernel_launch(void* const* d_in, const int* in_sizes, int n_in,
                              void* d_out, int out_size)
{
    const float* x_in     = (const float*)d_in[0];
    const int*   edge_feat= (const int*)  d_in[1];
    const int*   src      = (const int*)  d_in[2];
    const int*   dst      = (const int*)  d_in[3];
    const float* rel      = (const float*)d_in[4];
    const float* Wq       = (const float*)d_in[5];
    const float* bq       = (const float*)d_in[6];
    const float* Wk       = (const float*)d_in[7];
    const float* Wv       = (const float*)d_in[8];
    const float* Wo       = (const float*)d_in[9];
    const float* bo       = (const float*)d_in[10];
    const float* W1       = (const float*)d_in[11];
    const float* b1       = (const float*)d_in[12];
    const float* W2       = (const float*)d_in[13];
    const float* b2       = (const float*)d_in[14];
    const float* ln1g     = (const float*)d_in[15];
    const float* ln1b     = (const float*)d_in[16];
    const float* ln2g     = (const float*)d_in[17];
    const float* ln2b     = (const float*)d_in[18];

    float *q, *k, *v, *o, *tmp, *h, *xbuf, *ff;
    cudaGetSymbolAddress((void**)&q,    g_q);
    cudaGetSymbolAddress((void**)&k,    g_k);
    cudaGetSymbolAddress((void**)&v,    g_v);
    cudaGetSymbolAddress((void**)&o,    g_o);
    cudaGetSymbolAddress((void**)&tmp,  g_tmp);
    cudaGetSymbolAddress((void**)&h,    g_h);
    cudaGetSymbolAddress((void**)&xbuf, g_xbuf);
    cudaGetSymbolAddress((void**)&ff,   g_ff);

    zero_cnt_kernel<<<(N_NODES + 255) / 256, 256>>>();
    hist_kernel<<<(N_EDGES + 255) / 256, 256>>>(dst);
    scan_kernel<<<1, 1024>>>();
    scatter_kernel<<<(N_EDGES + 255) / 256, 256>>>(dst);

    const int warp_blocks = (N_NODES * 32 + 255) / 256;
    dim3 gHS(HS / BN, (N_NODES + BM - 1) / BM);
    dim3 gFF(FF_DIM / BN, (N_NODES + BM - 1) / BM);

    const float* xin = x_in;
    for (int l = 0; l < N_LAYERS; l++) {
        const float* wq = Wq + (size_t)l * HS * HS;
        const float* wk = Wk + (size_t)l * HS * HS;
        const float* wv = Wv + (size_t)l * HS * HS;
        const float* wo = Wo + (size_t)l * HS * HS;
        const float* w1 = W1 + (size_t)l * HS * FF_DIM;
        const float* w2 = W2 + (size_t)l * FF_DIM * HS;

        tf32_gemm_kernel<0><<<gHS, 256>>>(N_NODES, HS, HS, xin, wq, bq + l * HS, nullptr, q);
        tf32_gemm_kernel<0><<<gHS, 256>>>(N_NODES, HS, HS, xin, wk, nullptr, nullptr, k);
        tf32_gemm_kernel<0><<<gHS, 256>>>(N_NODES, HS, HS, xin, wv, nullptr, nullptr, v);

        edge_agg_kernel<<<warp_blocks, 256>>>(rel, edge_feat, src);

        tf32_gemm_kernel<2><<<gHS, 256>>>(N_NODES, HS, HS, o, wo, bo + l * HS, xin, tmp);
        ln_kernel<<<warp_blocks, 256>>>(tmp, ln1g + l * HS, ln1b + l * HS, h);

        tf32_gemm_kernel<1><<<gFF, 256>>>(N_NODES, HS, FF_DIM, h, w1, b1 + l * FF_DIM, nullptr, ff);
        tf32_gemm_kernel<2><<<gHS, 256>>>(N_NODES, FF_DIM, HS, ff, w2, b2 + l * HS, h, tmp);

        float* xnext = (l == N_LAYERS - 1) ? (float*)d_out : xbuf;
        ln_kernel<<<warp_blocks, 256>>>(tmp, ln2g + l * HS, ln2b + l * HS, xnext);
        xin = xbuf;
    }
}

// round 5
// speedup vs baseline: 3.0676x; 1.3223x over previous
#include <cuda_runtime.h>
#include <cuda_bf16.h>
#include <cstdint>

#define N_NODES 20000
#define N_EDGES 640000
#define HS 256
#define H_HEADS 8
#define DK 32
#define FF_DIM 1024
#define N_LAYERS 2

// ---------------- scratch (static device globals; no runtime alloc) ----------------
__device__ float g_q[(size_t)N_NODES * HS];
__device__ float g_k[(size_t)N_NODES * HS];
__device__ float g_v[(size_t)N_NODES * HS];
__device__ float g_o[(size_t)N_NODES * HS];
__device__ float g_tmp[(size_t)N_NODES * HS];
__device__ float g_h[(size_t)N_NODES * HS];
__device__ float g_xbuf[(size_t)N_NODES * HS];
__device__ float g_ff[(size_t)N_NODES * FF_DIM];

__device__ int g_cnt[N_NODES];
__device__ int g_rowptr[N_NODES + 1];
__device__ int g_cursor[N_NODES];
__device__ int g_eids[N_EDGES];

// ---------------- CSR build ----------------
__global__ void zero_cnt_kernel() {
    int i = blockIdx.x * blockDim.x + threadIdx.x;
    if (i < N_NODES) g_cnt[i] = 0;
}

__global__ void hist_kernel(const int* __restrict__ dst) {
    int i = blockIdx.x * blockDim.x + threadIdx.x;
    if (i < N_EDGES) atomicAdd(&g_cnt[dst[i]], 1);
}

__global__ void scan_kernel() {
    __shared__ int sh[1024];
    __shared__ int carry_sh;
    if (threadIdx.x == 0) carry_sh = 0;
    __syncthreads();
    for (int base = 0; base < N_NODES; base += 1024) {
        int i = base + threadIdx.x;
        int v = (i < N_NODES) ? g_cnt[i] : 0;
        sh[threadIdx.x] = v;
        __syncthreads();
        #pragma unroll
        for (int off = 1; off < 1024; off <<= 1) {
            int t = (threadIdx.x >= off) ? sh[threadIdx.x - off] : 0;
            __syncthreads();
            sh[threadIdx.x] += t;
            __syncthreads();
        }
        int incl = sh[threadIdx.x];
        int excl = incl - v + carry_sh;
        if (i < N_NODES) {
            g_rowptr[i] = excl;
            g_cursor[i] = excl;
        }
        __syncthreads();
        if (threadIdx.x == 1023) carry_sh += sh[1023];
        __syncthreads();
    }
    if (threadIdx.x == 0) g_rowptr[N_NODES] = carry_sh;
}

__global__ void scatter_kernel(const int* __restrict__ dst) {
    int i = blockIdx.x * blockDim.x + threadIdx.x;
    if (i < N_EDGES) {
        int p = atomicAdd(&g_cursor[dst[i]], 1);
        g_eids[p] = i;
    }
}

// ---------------- BF16 tensor-core GEMM (persistent CTAs) ----------------
// C[M,Nc] = epi(A[M,K] @ B[K,Nc] + bias [+ res]) ; fp32 accumulate.
// MODE 0: +bias (nullable)   MODE 1: relu(+bias)   MODE 2: +bias +res
#define BM 128
#define BN 128
#define BKF 32              // K floats per chunk
#define KW 16               // bf16x2 words per chunk (= BKF/2)
#define SPAD 8
#define SSTRIDE (BM + SPAD) // 136 words

__device__ __forceinline__ uint32_t packbf2(float lo, float hi) {
    __nv_bfloat162 h = __float22bfloat162_rn(make_float2(lo, hi));
    return *reinterpret_cast<uint32_t*>(&h);
}

__device__ __forceinline__ void mma_bf16(float4& c, const uint32_t a[4], const uint32_t b[2]) {
    asm volatile(
        "mma.sync.aligned.m16n8k16.row.col.f32.bf16.bf16.f32 "
        "{%0,%1,%2,%3}, {%4,%5,%6,%7}, {%8,%9}, {%0,%1,%2,%3};"
        : "+f"(c.x), "+f"(c.y), "+f"(c.z), "+f"(c.w)
        : "r"(a[0]), "r"(a[1]), "r"(a[2]), "r"(a[3]), "r"(b[0]), "r"(b[1]));
}

template <int MODE>
__global__ __launch_bounds__(256, 2) void bf16_gemm_kernel(
    int M, int K, int Nc, int gn, int total_tiles,
    const float* __restrict__ A,
    const float* __restrict__ B,
    const float* __restrict__ bias,
    const float* __restrict__ res,
    float* __restrict__ C)
{
    __shared__ uint32_t As[2][KW][SSTRIDE];   // word = {A[m][2k], A[m][2k+1]}, laid [k][m]
    __shared__ uint32_t Bs[2][KW][SSTRIDE];   // word = {B[2k][n], B[2k+1][n]}, laid [k][n]

    const int tid  = threadIdx.x;
    const int lane = tid & 31;
    const int warp = tid >> 5;
    const int g  = lane >> 2;   // 0..7
    const int tg = lane & 3;    // 0..3
    const int wm = (warp >> 2) * 64;   // 0 / 64
    const int wn = (warp & 3) * 32;    // 0 / 32 / 64 / 96

    // A loads: 4 per thread; idx = tid + 256*i -> m = idx>>3, kf = (idx&7)*4
    const int a_m   = tid >> 3;        // +32 per i
    const int a_kf  = (tid & 7) * 4;   // 0,4,...,28
    const int a_kw  = a_kf >> 1;       // word row (and +1)
    // B loads: 2 per thread; idx = tid + 256*i -> kp = idx>>5, n4 = (idx&31)*4
    const int b_kp  = tid >> 5;        // +8 per i
    const int b_n4  = (tid & 31) * 4;

    const int nch = K >> 5;            // chunks of 32 k-floats (even for all our K)

    for (int t = blockIdx.x; t < total_tiles; t += gridDim.x) {
        const int m0 = (t / gn) * BM;
        const int n0 = (t % gn) * BN;
        __syncthreads();   // smem from previous tile fully consumed

        float4 acc[4][4];
        #pragma unroll
        for (int i = 0; i < 4; i++)
            #pragma unroll
            for (int j = 0; j < 4; j++) acc[i][j] = make_float4(0.f, 0.f, 0.f, 0.f);

        float4 aR[4], bRe[2], bRo[2];

        // ---- prime chunk 0 into buffer 0 ----
        #pragma unroll
        for (int i = 0; i < 4; i++) {
            const int m = a_m + 32 * i;
            float4 av = make_float4(0.f, 0.f, 0.f, 0.f);
            if (m0 + m < M) av = *(const float4*)(A + (size_t)(m0 + m) * K + a_kf);
            As[0][a_kw][m]     = packbf2(av.x, av.y);
            As[0][a_kw + 1][m] = packbf2(av.z, av.w);
        }
        #pragma unroll
        for (int i = 0; i < 2; i++) {
            const int kp = b_kp + 8 * i;
            const float* bp = B + (size_t)(2 * kp) * Nc + n0 + b_n4;
            float4 be = *(const float4*)bp;
            float4 bo = *(const float4*)(bp + Nc);
            uint4 w = make_uint4(packbf2(be.x, bo.x), packbf2(be.y, bo.y),
                                 packbf2(be.z, bo.z), packbf2(be.w, bo.w));
            *(uint4*)(&Bs[0][kp][b_n4]) = w;
        }
        __syncthreads();

        for (int ch = 0; ch < nch; ch++) {
            const int cur = ch & 1;
            const int nxt = cur ^ 1;
            const bool has_next = (ch + 1 < nch);

            if (has_next) {
                const int k0 = (ch + 1) * BKF;
                #pragma unroll
                for (int i = 0; i < 4; i++) {
                    const int m = a_m + 32 * i;
                    aR[i] = make_float4(0.f, 0.f, 0.f, 0.f);
                    if (m0 + m < M) aR[i] = *(const float4*)(A + (size_t)(m0 + m) * K + k0 + a_kf);
                }
                #pragma unroll
                for (int i = 0; i < 2; i++) {
                    const int kp = b_kp + 8 * i;
                    const float* bp = B + (size_t)(k0 + 2 * kp) * Nc + n0 + b_n4;
                    bRe[i] = *(const float4*)bp;
                    bRo[i] = *(const float4*)(bp + Nc);
                }
            }

            // ---- compute: two m16n8k16 k-steps over this 32-float chunk ----
            #pragma unroll
            for (int ks = 0; ks < KW; ks += 8) {
                uint32_t afr[4][4];
                uint32_t bfr[4][2];
                #pragma unroll
                for (int mt = 0; mt < 4; mt++) {
                    const int m = wm + mt * 16 + g;
                    afr[mt][0] = As[cur][ks + tg][m];
                    afr[mt][1] = As[cur][ks + tg][m + 8];
                    afr[mt][2] = As[cur][ks + tg + 4][m];
                    afr[mt][3] = As[cur][ks + tg + 4][m + 8];
                }
                #pragma unroll
                for (int nt = 0; nt < 4; nt++) {
                    const int n = wn + nt * 8 + g;
                    bfr[nt][0] = Bs[cur][ks + tg][n];
                    bfr[nt][1] = Bs[cur][ks + tg + 4][n];
                }
                #pragma unroll
                for (int mt = 0; mt < 4; mt++)
                    #pragma unroll
                    for (int nt = 0; nt < 4; nt++)
                        mma_bf16(acc[mt][nt], afr[mt], bfr[nt]);
            }

            if (has_next) {
                #pragma unroll
                for (int i = 0; i < 4; i++) {
                    const int m = a_m + 32 * i;
                    As[nxt][a_kw][m]     = packbf2(aR[i].x, aR[i].y);
                    As[nxt][a_kw + 1][m] = packbf2(aR[i].z, aR[i].w);
                }
                #pragma unroll
                for (int i = 0; i < 2; i++) {
                    const int kp = b_kp + 8 * i;
                    uint4 w = make_uint4(packbf2(bRe[i].x, bRo[i].x), packbf2(bRe[i].y, bRo[i].y),
                                         packbf2(bRe[i].z, bRo[i].z), packbf2(bRe[i].w, bRo[i].w));
                    *(uint4*)(&Bs[nxt][kp][b_n4]) = w;
                }
                __syncthreads();
            }
        }

        // ---- epilogue ----
        #pragma unroll
        for (int mt = 0; mt < 4; mt++) {
            #pragma unroll
            for (int nt = 0; nt < 4; nt++) {
                const int row0 = m0 + wm + mt * 16 + g;
                const int row1 = row0 + 8;
                const int col  = n0 + wn + nt * 8 + tg * 2;
                float2 v0 = make_float2(acc[mt][nt].x, acc[mt][nt].y);
                float2 v1 = make_float2(acc[mt][nt].z, acc[mt][nt].w);
                if (bias) {
                    float2 bb = *(const float2*)(bias + col);
                    v0.x += bb.x; v0.y += bb.y;
                    v1.x += bb.x; v1.y += bb.y;
                }
                if (MODE == 2) {
                    if (row0 < M) {
                        float2 r0 = *(const float2*)(res + (size_t)row0 * Nc + col);
                        v0.x += r0.x; v0.y += r0.y;
                    }
                    if (row1 < M) {
                        float2 r1 = *(const float2*)(res + (size_t)row1 * Nc + col);
                        v1.x += r1.x; v1.y += r1.y;
                    }
                }
                if (MODE == 1) {
                    v0.x = fmaxf(v0.x, 0.f); v0.y = fmaxf(v0.y, 0.f);
                    v1.x = fmaxf(v1.x, 0.f); v1.y = fmaxf(v1.y, 0.f);
                }
                if (row0 < M) *(float2*)(C + (size_t)row0 * Nc + col) = v0;
                if (row1 < M) *(float2*)(C + (size_t)row1 * Nc + col) = v1;
            }
        }
    }
}

// ---------------- edge aggregation: one warp per destination node ----------------
__global__ void edge_agg_kernel(const float* __restrict__ rel,
                                const int* __restrict__ edge_feat,
                                const int* __restrict__ src)
{
    int gw = (blockIdx.x * blockDim.x + threadIdx.x) >> 5;
    int lane = threadIdx.x & 31;
    if (gw >= N_NODES) return;

    const float4* qr = (const float4*)(g_q + (size_t)gw * HS);
    float4 q0 = qr[2 * lane], q1 = qr[2 * lane + 1];

    float4 a0 = make_float4(0.f, 0.f, 0.f, 0.f);
    float4 a1 = make_float4(0.f, 0.f, 0.f, 0.f);
    float zsum = 0.f;

    int beg = g_rowptr[gw], end = g_rowptr[gw + 1];
    int ecol = 2 * (lane & 3);
    const float invs = 0.17677669529663687f;

    for (int j = beg; j < end; j++) {
        int e = g_eids[j];
        int s = src[e];
        int r = edge_feat[e];
        const float4* kr = (const float4*)(g_k + (size_t)s * HS);
        const float4* vr = (const float4*)(g_v + (size_t)s * HS);
        const float4* er = (const float4*)(rel + (size_t)r * DK);
        float4 k0 = kr[2 * lane], k1 = kr[2 * lane + 1];
        float4 e0 = er[ecol], e1 = er[ecol + 1];

        float d = (k0.x + e0.x) * q0.x + (k0.y + e0.y) * q0.y
                + (k0.z + e0.z) * q0.z + (k0.w + e0.w) * q0.w
                + (k1.x + e1.x) * q1.x + (k1.y + e1.y) * q1.y
                + (k1.z + e1.z) * q1.z + (k1.w + e1.w) * q1.w;
        d += __shfl_xor_sync(0xffffffffu, d, 1);
        d += __shfl_xor_sync(0xffffffffu, d, 2);
        float sc = __expf(fminf(fmaxf(d * invs, -10.f), 10.f));

        float4 v0 = vr[2 * lane], v1 = vr[2 * lane + 1];
        a0.x += (v0.x + e0.x) * sc; a0.y += (v0.y + e0.y) * sc;
        a0.z += (v0.z + e0.z) * sc; a0.w += (v0.w + e0.w) * sc;
        a1.x += (v1.x + e1.x) * sc; a1.y += (v1.y + e1.y) * sc;
        a1.z += (v1.z + e1.z) * sc; a1.w += (v1.w + e1.w) * sc;
        zsum += sc;
    }

    float inv = 1.f / zsum;
    float4* orow = (float4*)(g_o + (size_t)gw * HS);
    orow[2 * lane]     = make_float4(a0.x * inv, a0.y * inv, a0.z * inv, a0.w * inv);
    orow[2 * lane + 1] = make_float4(a1.x * inv, a1.y * inv, a1.z * inv, a1.w * inv);
}

// ---------------- layernorm: one warp per row ----------------
__global__ void ln_kernel(const float* __restrict__ in,
                          const float* __restrict__ gamma,
                          const float* __restrict__ beta,
                          float* __restrict__ out)
{
    int gw = (blockIdx.x * blockDim.x + threadIdx.x) >> 5;
    int lane = threadIdx.x & 31;
    if (gw >= N_NODES) return;

    const float4* row = (const float4*)(in + (size_t)gw * HS);
    float4 x0 = row[2 * lane], x1 = row[2 * lane + 1];

    float s = x0.x + x0.y + x0.z + x0.w + x1.x + x1.y + x1.z + x1.w;
    #pragma unroll
    for (int off = 16; off; off >>= 1) s += __shfl_xor_sync(0xffffffffu, s, off);
    float mean = s * (1.f / HS);

    float d0 = x0.x - mean, d1 = x0.y - mean, d2 = x0.z - mean, d3 = x0.w - mean;
    float d4 = x1.x - mean, d5 = x1.y - mean, d6 = x1.z - mean, d7 = x1.w - mean;
    float ss = d0 * d0 + d1 * d1 + d2 * d2 + d3 * d3 + d4 * d4 + d5 * d5 + d6 * d6 + d7 * d7;
    #pragma unroll
    for (int off = 16; off; off >>= 1) ss += __shfl_xor_sync(0xffffffffu, ss, off);
    float rstd = rsqrtf(ss * (1.f / HS) + 1e-5f);

    const float4* gr = (const float4*)gamma;
    const float4* br = (const float4*)beta;
    float4 gg0 = gr[2 * lane], gg1 = gr[2 * lane + 1];
    float4 bb0 = br[2 * lane], bb1 = br[2 * lane + 1];

    float4* orow = (float4*)(out + (size_t)gw * HS);
    orow[2 * lane] = make_float4(d0 * rstd * gg0.x + bb0.x, d1 * rstd * gg0.y + bb0.y,
                                 d2 * rstd * gg0.z + bb0.z, d3 * rstd * gg0.w + bb0.w);
    orow[2 * lane + 1] = make_float4(d4 * rstd * gg1.x + bb1.x,
                                     d5 * rstd * gg1.y + bb1.y,
                                     d6 * rstd * gg1.z + bb1.z,
                                     d7 * rstd * gg1.w + bb1.w);
}

// ---------------- host orchestration ----------------
extern "C" void kernel_launch(void* const* d_in, const int* in_sizes, int n_in,
                              void* d_out, int out_size)
{
    const float* x_in     = (const float*)d_in[0];
    const int*   edge_feat= (const int*)  d_in[1];
    const int*   src      = (const int*)  d_in[2];
    const int*   dst      = (const int*)  d_in[3];
    const float* rel      = (const float*)d_in[4];
    const float* Wq       = (const float*)d_in[5];
    const float* bq       = (const float*)d_in[6];
    const float* Wk       = (const float*)d_in[7];
    const float* Wv       = (const float*)d_in[8];
    const float* Wo       = (const float*)d_in[9];
    const float* bo       = (const float*)d_in[10];
    const float* W1       = (const float*)d_in[11];
    const float* b1       = (const float*)d_in[12];
    const float* W2       = (const float*)d_in[13];
    const float* b2       = (const float*)d_in[14];
    const float* ln1g     = (const float*)d_in[15];
    const float* ln1b     = (const float*)d_in[16];
    const float* ln2g     = (const float*)d_in[17];
    const float* ln2b     = (const float*)d_in[18];

    float *q, *k, *v, *o, *tmp, *h, *xbuf, *ff;
    cudaGetSymbolAddress((void**)&q,    g_q);
    cudaGetSymbolAddress((void**)&k,    g_k);
    cudaGetSymbolAddress((void**)&v,    g_v);
    cudaGetSymbolAddress((void**)&o,    g_o);
    cudaGetSymbolAddress((void**)&tmp,  g_tmp);
    cudaGetSymbolAddress((void**)&h,    g_h);
    cudaGetSymbolAddress((void**)&xbuf, g_xbuf);
    cudaGetSymbolAddress((void**)&ff,   g_ff);

    zero_cnt_kernel<<<(N_NODES + 255) / 256, 256>>>();
    hist_kernel<<<(N_EDGES + 255) / 256, 256>>>(dst);
    scan_kernel<<<1, 1024>>>();
    scatter_kernel<<<(N_EDGES + 255) / 256, 256>>>(dst);

    const int warp_blocks = (N_NODES * 32 + 255) / 256;
    const int GM = (N_NODES + BM - 1) / BM;   // 157
    const int gnHS = HS / BN;                  // 2
    const int gnFF = FF_DIM / BN;              // 8
    const int tilesHS = GM * gnHS;             // 314
    const int tilesFF = GM * gnFF;             // 1256
    const int PGRID = 296;                     // 148 SMs x 2 CTAs

    const float* xin = x_in;
    for (int l = 0; l < N_LAYERS; l++) {
        const float* wq = Wq + (size_t)l * HS * HS;
        const float* wk = Wk + (size_t)l * HS * HS;
        const float* wv = Wv + (size_t)l * HS * HS;
        const float* wo = Wo + (size_t)l * HS * HS;
        const float* w1 = W1 + (size_t)l * HS * FF_DIM;
        const float* w2 = W2 + (size_t)l * FF_DIM * HS;

        bf16_gemm_kernel<0><<<PGRID, 256>>>(N_NODES, HS, HS, gnHS, tilesHS, xin, wq, bq + l * HS, nullptr, q);
        bf16_gemm_kernel<0><<<PGRID, 256>>>(N_NODES, HS, HS, gnHS, tilesHS, xin, wk, nullptr, nullptr, k);
        bf16_gemm_kernel<0><<<PGRID, 256>>>(N_NODES, HS, HS, gnHS, tilesHS, xin, wv, nullptr, nullptr, v);

        edge_agg_kernel<<<warp_blocks, 256>>>(rel, edge_feat, src);

        bf16_gemm_kernel<2><<<PGRID, 256>>>(N_NODES, HS, HS, gnHS, tilesHS, o, wo, bo + l * HS, xin, tmp);
        ln_kernel<<<warp_blocks, 256>>>(tmp, ln1g + l * HS, ln1b + l * HS, h);

        bf16_gemm_kernel<1><<<PGRID, 256>>>(N_NODES, HS, FF_DIM, gnFF, tilesFF, h, w1, b1 + l * FF_DIM, nullptr, ff);
        bf16_gemm_kernel<2><<<PGRID, 256>>>(N_NODES, FF_DIM, HS, gnHS, tilesHS, ff, w2, b2 + l * HS, h, tmp);

        float* xnext = (l == N_LAYERS - 1) ? (float*)d_out : xbuf;
        ln_kernel<<<warp_blocks, 256>>>(tmp, ln2g + l * HS, ln2b + l * HS, xnext);
        xin = xbuf;
    }
}

// round 8
// speedup vs baseline: 3.2894x; 1.0723x over previous
#include <cuda_runtime.h>
#include <cuda_bf16.h>
#include <cstdint>

#define N_NODES 20000
#define N_EDGES 640000
#define HS 256
#define H_HEADS 8
#define DK 32
#define FF_DIM 1024
#define N_LAYERS 2

// ---------------- scratch (static device globals; no runtime alloc) ----------------
__device__ float g_q[(size_t)N_NODES * HS];
__device__ float g_k[(size_t)N_NODES * HS];
__device__ float g_v[(size_t)N_NODES * HS];
__device__ float g_o[(size_t)N_NODES * HS];
__device__ float g_tmp[(size_t)N_NODES * HS];
__device__ float g_h[(size_t)N_NODES * HS];
__device__ float g_xbuf[(size_t)N_NODES * HS];
__device__ float g_ff[(size_t)N_NODES * FF_DIM];

__device__ int g_cnt[N_NODES];
__device__ int g_rowptr[N_NODES + 1];
__device__ int g_cursor[N_NODES];
__device__ int g_eids[N_EDGES];

// ---------------- CSR build ----------------
__global__ void hist_kernel(const int* __restrict__ dst) {
    int i = blockIdx.x * blockDim.x + threadIdx.x;
    if (i < N_EDGES) atomicAdd(&g_cnt[dst[i]], 1);
}

__global__ void scan_kernel() {
    __shared__ int sh[1024];
    __shared__ int carry_sh;
    if (threadIdx.x == 0) carry_sh = 0;
    __syncthreads();
    for (int base = 0; base < N_NODES; base += 1024) {
        int i = base + threadIdx.x;
        int v = (i < N_NODES) ? g_cnt[i] : 0;
        sh[threadIdx.x] = v;
        __syncthreads();
        #pragma unroll
        for (int off = 1; off < 1024; off <<= 1) {
            int t = (threadIdx.x >= off) ? sh[threadIdx.x - off] : 0;
            __syncthreads();
            sh[threadIdx.x] += t;
            __syncthreads();
        }
        int incl = sh[threadIdx.x];
        int excl = incl - v + carry_sh;
        if (i < N_NODES) {
            g_rowptr[i] = excl;
            g_cursor[i] = excl;
        }
        __syncthreads();
        if (threadIdx.x == 1023) carry_sh += sh[1023];
        __syncthreads();
    }
    if (threadIdx.x == 0) g_rowptr[N_NODES] = carry_sh;
}

__global__ void scatter_kernel(const int* __restrict__ dst) {
    int i = blockIdx.x * blockDim.x + threadIdx.x;
    if (i < N_EDGES) {
        int p = atomicAdd(&g_cursor[dst[i]], 1);
        g_eids[p] = i;
    }
}

// ---------------- BF16 tensor-core GEMM (persistent CTAs) ----------------
// C[M,Nc] = epi(A[M,K] @ B[K,Nc] + bias [+ res]) ; fp32 accumulate.
// MODE 0: +bias (nullable)   MODE 1: relu(+bias)   MODE 2: +bias +res
#define BM 128
#define BN 128
#define BKF 32              // K floats per chunk
#define KW 16               // bf16x2 words per chunk (= BKF/2)
#define SPAD 8
#define SSTRIDE (BM + SPAD) // 136 words

__device__ __forceinline__ uint32_t packbf2(float lo, float hi) {
    __nv_bfloat162 h = __float22bfloat162_rn(make_float2(lo, hi));
    return *reinterpret_cast<uint32_t*>(&h);
}

__device__ __forceinline__ void mma_bf16(float4& c, const uint32_t a[4], const uint32_t b[2]) {
    asm volatile(
        "mma.sync.aligned.m16n8k16.row.col.f32.bf16.bf16.f32 "
        "{%0,%1,%2,%3}, {%4,%5,%6,%7}, {%8,%9}, {%0,%1,%2,%3};"
        : "+f"(c.x), "+f"(c.y), "+f"(c.z), "+f"(c.w)
        : "r"(a[0]), "r"(a[1]), "r"(a[2]), "r"(a[3]), "r"(b[0]), "r"(b[1]));
}

typedef uint32_t SmemBuf[2][KW][SSTRIDE];

template <int MODE>
__device__ __forceinline__ void gemm_tile(
    SmemBuf& As, SmemBuf& Bs,
    int M, int K, int Nc, int m0, int n0,
    const float* __restrict__ A,
    const float* __restrict__ B,
    const float* __restrict__ bias,
    const float* __restrict__ res,
    float* __restrict__ C)
{
    const int tid  = threadIdx.x;
    const int lane = tid & 31;
    const int warp = tid >> 5;
    const int g  = lane >> 2;
    const int tg = lane & 3;
    const int wm = (warp >> 2) * 64;
    const int wn = (warp & 3) * 32;

    const int a_m   = tid >> 3;
    const int a_kf  = (tid & 7) * 4;
    const int a_kw  = a_kf >> 1;
    const int b_kp  = tid >> 5;
    const int b_n4  = (tid & 31) * 4;

    const int nch = K >> 5;

    float4 acc[4][4];
    #pragma unroll
    for (int i = 0; i < 4; i++)
        #pragma unroll
        for (int j = 0; j < 4; j++) acc[i][j] = make_float4(0.f, 0.f, 0.f, 0.f);

    float4 aR[4], bRe[2], bRo[2];

    // prime chunk 0 into buffer 0
    #pragma unroll
    for (int i = 0; i < 4; i++) {
        const int m = a_m + 32 * i;
        float4 av = make_float4(0.f, 0.f, 0.f, 0.f);
        if (m0 + m < M) av = *(const float4*)(A + (size_t)(m0 + m) * K + a_kf);
        As[0][a_kw][m]     = packbf2(av.x, av.y);
        As[0][a_kw + 1][m] = packbf2(av.z, av.w);
    }
    #pragma unroll
    for (int i = 0; i < 2; i++) {
        const int kp = b_kp + 8 * i;
        const float* bp = B + (size_t)(2 * kp) * Nc + n0 + b_n4;
        float4 be = *(const float4*)bp;
        float4 bo = *(const float4*)(bp + Nc);
        uint4 w = make_uint4(packbf2(be.x, bo.x), packbf2(be.y, bo.y),
                             packbf2(be.z, bo.z), packbf2(be.w, bo.w));
        *(uint4*)(&Bs[0][kp][b_n4]) = w;
    }
    __syncthreads();

    for (int ch = 0; ch < nch; ch++) {
        const int cur = ch & 1;
        const int nxt = cur ^ 1;
        const bool has_next = (ch + 1 < nch);

        if (has_next) {
            const int k0 = (ch + 1) * BKF;
            #pragma unroll
            for (int i = 0; i < 4; i++) {
                const int m = a_m + 32 * i;
                aR[i] = make_float4(0.f, 0.f, 0.f, 0.f);
                if (m0 + m < M) aR[i] = *(const float4*)(A + (size_t)(m0 + m) * K + k0 + a_kf);
            }
            #pragma unroll
            for (int i = 0; i < 2; i++) {
                const int kp = b_kp + 8 * i;
                const float* bp = B + (size_t)(k0 + 2 * kp) * Nc + n0 + b_n4;
                bRe[i] = *(const float4*)bp;
                bRo[i] = *(const float4*)(bp + Nc);
            }
        }

        #pragma unroll
        for (int ks = 0; ks < KW; ks += 8) {
            uint32_t afr[4][4];
            uint32_t bfr[4][2];
            #pragma unroll
            for (int mt = 0; mt < 4; mt++) {
                const int m = wm + mt * 16 + g;
                afr[mt][0] = As[cur][ks + tg][m];
                afr[mt][1] = As[cur][ks + tg][m + 8];
                afr[mt][2] = As[cur][ks + tg + 4][m];
                afr[mt][3] = As[cur][ks + tg + 4][m + 8];
            }
            #pragma unroll
            for (int nt = 0; nt < 4; nt++) {
                const int n = wn + nt * 8 + g;
                bfr[nt][0] = Bs[cur][ks + tg][n];
                bfr[nt][1] = Bs[cur][ks + tg + 4][n];
            }
            #pragma unroll
            for (int mt = 0; mt < 4; mt++)
                #pragma unroll
                for (int nt = 0; nt < 4; nt++)
                    mma_bf16(acc[mt][nt], afr[mt], bfr[nt]);
        }

        if (has_next) {
            #pragma unroll
            for (int i = 0; i < 4; i++) {
                const int m = a_m + 32 * i;
                As[nxt][a_kw][m]     = packbf2(aR[i].x, aR[i].y);
                As[nxt][a_kw + 1][m] = packbf2(aR[i].z, aR[i].w);
            }
            #pragma unroll
            for (int i = 0; i < 2; i++) {
                const int kp = b_kp + 8 * i;
                uint4 w = make_uint4(packbf2(bRe[i].x, bRo[i].x), packbf2(bRe[i].y, bRo[i].y),
                                     packbf2(bRe[i].z, bRo[i].z), packbf2(bRe[i].w, bRo[i].w));
                *(uint4*)(&Bs[nxt][kp][b_n4]) = w;
            }
            __syncthreads();
        }
    }

    // epilogue
    #pragma unroll
    for (int mt = 0; mt < 4; mt++) {
        #pragma unroll
        for (int nt = 0; nt < 4; nt++) {
            const int row0 = m0 + wm + mt * 16 + g;
            const int row1 = row0 + 8;
            const int col  = n0 + wn + nt * 8 + tg * 2;
            float2 v0 = make_float2(acc[mt][nt].x, acc[mt][nt].y);
            float2 v1 = make_float2(acc[mt][nt].z, acc[mt][nt].w);
            if (bias) {
                float2 bb = *(const float2*)(bias + col);
                v0.x += bb.x; v0.y += bb.y;
                v1.x += bb.x; v1.y += bb.y;
            }
            if (MODE == 2) {
                if (row0 < M) {
                    float2 r0 = *(const float2*)(res + (size_t)row0 * Nc + col);
                    v0.x += r0.x; v0.y += r0.y;
                }
                if (row1 < M) {
                    float2 r1 = *(const float2*)(res + (size_t)row1 * Nc + col);
                    v1.x += r1.x; v1.y += r1.y;
                }
            }
            if (MODE == 1) {
                v0.x = fmaxf(v0.x, 0.f); v0.y = fmaxf(v0.y, 0.f);
                v1.x = fmaxf(v1.x, 0.f); v1.y = fmaxf(v1.y, 0.f);
            }
            if (row0 < M) *(float2*)(C + (size_t)row0 * Nc + col) = v0;
            if (row1 < M) *(float2*)(C + (size_t)row1 * Nc + col) = v1;
        }
    }
}

template <int MODE>
__global__ __launch_bounds__(256, 2) void bf16_gemm_kernel(
    int M, int K, int Nc, int gn, int total_tiles,
    const float* __restrict__ A,
    const float* __restrict__ B,
    const float* __restrict__ bias,
    const float* __restrict__ res,
    float* __restrict__ C)
{
    __shared__ SmemBuf As;
    __shared__ SmemBuf Bs;
    for (int t = blockIdx.x; t < total_tiles; t += gridDim.x) {
        const int m0 = (t / gn) * BM;
        const int n0 = (t % gn) * BN;
        __syncthreads();
        gemm_tile<MODE>(As, Bs, M, K, Nc, m0, n0, A, B, bias, res, C);
    }
}

// fused q/k/v: three GEMMs sharing A, one persistent launch
__global__ __launch_bounds__(256, 2) void bf16_gemm_qkv_kernel(
    int M, int K, int Nc, int gn, int tiles_per,
    const float* __restrict__ A,
    const float* __restrict__ Bq,
    const float* __restrict__ Bk,
    const float* __restrict__ Bv,
    const float* __restrict__ biasq,
    float* __restrict__ Cq,
    float* __restrict__ Ck,
    float* __restrict__ Cv)
{
    __shared__ SmemBuf As;
    __shared__ SmemBuf Bs;
    const int total = 3 * tiles_per;
    for (int t = blockIdx.x; t < total; t += gridDim.x) {
        const int which = t / tiles_per;
        const int tt = t % tiles_per;
        const int m0 = (tt / gn) * BM;
        const int n0 = (tt % gn) * BN;
        const float* B = (which == 0) ? Bq : (which == 1) ? Bk : Bv;
        float* C       = (which == 0) ? Cq : (which == 1) ? Ck : Cv;
        const float* bias = (which == 0) ? biasq : nullptr;
        __syncthreads();
        gemm_tile<0>(As, Bs, M, K, Nc, m0, n0, A, B, bias, nullptr, C);
    }
}

// ---------------- edge aggregation: one warp per destination node ----------------
// Software-pipelined: 32 edge indices fetched lane-parallel per chunk; edge j+1's
// k/v/e rows are loaded while edge j computes.
__global__ void edge_agg_kernel(const float* __restrict__ rel,
                                const int* __restrict__ edge_feat,
                                const int* __restrict__ src)
{
    int gw = (blockIdx.x * blockDim.x + threadIdx.x) >> 5;
    int lane = threadIdx.x & 31;
    if (gw >= N_NODES) return;

    const float4* qr = (const float4*)(g_q + (size_t)gw * HS);
    float4 q0 = qr[2 * lane], q1 = qr[2 * lane + 1];

    float4 a0 = make_float4(0.f, 0.f, 0.f, 0.f);
    float4 a1 = make_float4(0.f, 0.f, 0.f, 0.f);
    float zsum = 0.f;

    const int beg = g_rowptr[gw], end = g_rowptr[gw + 1];
    const int ecol = 2 * (lane & 3);
    const float invs = 0.17677669529663687f;  // 1/sqrt(32)

    for (int base = beg; base < end; base += 32) {
        const int cnt = min(32, end - base);
        // lane-parallel index gather for up to 32 edges
        int s_l = 0, r_l = 0;
        if (base + lane < end) {
            int e = g_eids[base + lane];
            s_l = __ldg(&src[e]);
            r_l = __ldg(&edge_feat[e]);
        }

        // prime edge 0
        int s_c = __shfl_sync(0xffffffffu, s_l, 0);
        int r_c = __shfl_sync(0xffffffffu, r_l, 0);
        const float4* kr = (const float4*)(g_k + (size_t)s_c * HS);
        const float4* vr = (const float4*)(g_v + (size_t)s_c * HS);
        const float4* er = (const float4*)(rel + (size_t)r_c * DK);
        float4 k0 = kr[2 * lane], k1 = kr[2 * lane + 1];
        float4 v0 = vr[2 * lane], v1 = vr[2 * lane + 1];
        float4 e0 = er[ecol],     e1 = er[ecol + 1];

        for (int j = 0; j < cnt; j++) {
            // capture current edge data
            float4 K0 = k0, K1 = k1, V0 = v0, V1 = v1, E0 = e0, E1 = e1;
            // issue next edge's loads before computing
            if (j + 1 < cnt) {
                int s_n = __shfl_sync(0xffffffffu, s_l, j + 1);
                int r_n = __shfl_sync(0xffffffffu, r_l, j + 1);
                const float4* krn = (const float4*)(g_k + (size_t)s_n * HS);
                const float4* vrn = (const float4*)(g_v + (size_t)s_n * HS);
                const float4* ern = (const float4*)(rel + (size_t)r_n * DK);
                k0 = krn[2 * lane]; k1 = krn[2 * lane + 1];
                v0 = vrn[2 * lane]; v1 = vrn[2 * lane + 1];
                e0 = ern[ecol];     e1 = ern[ecol + 1];
            }

            float d = (K0.x + E0.x) * q0.x + (K0.y + E0.y) * q0.y
                    + (K0.z + E0.z) * q0.z + (K0.w + E0.w) * q0.w
                    + (K1.x + E1.x) * q1.x + (K1.y + E1.y) * q1.y
                    + (K1.z + E1.z) * q1.z + (K1.w + E1.w) * q1.w;
            d += __shfl_xor_sync(0xffffffffu, d, 1);
            d += __shfl_xor_sync(0xffffffffu, d, 2);
            float sc = __expf(fminf(fmaxf(d * invs, -10.f), 10.f));

            a0.x += (V0.x + E0.x) * sc; a0.y += (V0.y + E0.y) * sc;
            a0.z += (V0.z + E0.z) * sc; a0.w += (V0.w + E0.w) * sc;
            a1.x += (V1.x + E1.x) * sc; a1.y += (V1.y + E1.y) * sc;
            a1.z += (V1.z + E1.z) * sc; a1.w += (V1.w + E1.w) * sc;
            zsum += sc;
        }
    }

    float inv = 1.f / zsum;
    float4* orow = (float4*)(g_o + (size_t)gw * HS);
    orow[2 * lane]     = make_float4(a0.x * inv, a0.y * inv, a0.z * inv, a0.w * inv);
    orow[2 * lane + 1] = make_float4(a1.x * inv, a1.y * inv, a1.z * inv, a1.w * inv);
}

// ---------------- layernorm: one warp per row ----------------
__global__ void ln_kernel(const float* __restrict__ in,
                          const float* __restrict__ gamma,
                          const float* __restrict__ beta,
                          float* __restrict__ out)
{
    int gw = (blockIdx.x * blockDim.x + threadIdx.x) >> 5;
    int lane = threadIdx.x & 31;
    if (gw >= N_NODES) return;

    const float4* row = (const float4*)(in + (size_t)gw * HS);
    float4 x0 = row[2 * lane], x1 = row[2 * lane + 1];

    float s = x0.x + x0.y + x0.z + x0.w + x1.x + x1.y + x1.z + x1.w;
    #pragma unroll
    for (int off = 16; off; off >>= 1) s += __shfl_xor_sync(0xffffffffu, s, off);
    float mean = s * (1.f / HS);

    float d0 = x0.x - mean, d1 = x0.y - mean, d2 = x0.z - mean, d3 = x0.w - mean;
    float d4 = x1.x - mean, d5 = x1.y - mean, d6 = x1.z - mean, d7 = x1.w - mean;
    float ss = d0 * d0 + d1 * d1 + d2 * d2 + d3 * d3 + d4 * d4 + d5 * d5 + d6 * d6 + d7 * d7;
    #pragma unroll
    for (int off = 16; off; off >>= 1) ss += __shfl_xor_sync(0xffffffffu, ss, off);
    float rstd = rsqrtf(ss * (1.f / HS) + 1e-5f);

    const float4* gr = (const float4*)gamma;
    const float4* br = (const float4*)beta;
    float4 gg0 = gr[2 * lane], gg1 = gr[2 * lane + 1];
    float4 bb0 = br[2 * lane], bb1 = br[2 * lane + 1];

    float4* orow = (float4*)(out + (size_t)gw * HS);
    orow[2 * lane] = make_float4(d0 * rstd * gg0.x + bb0.x, d1 * rstd * gg0.y + bb0.y,
                                 d2 * rstd * gg0.z + bb0.z, d3 * rstd * gg0.w + bb0.w);
    orow[2 * lane + 1] = make_float4(d4 * rstd * gg1.x + bb1.x,
                                     d5 * rstd * gg1.y + bb1.y,
                                     d6 * rstd * gg1.z + bb1.z,
                                     d7 * rstd * gg1.w + bb1.w);
}

// ---------------- host orchestration ----------------
extern "C" void kernel_launch(void* const* d_in, const int* in_sizes, int n_in,
                              void* d_out, int out_size)
{
    const float* x_in     = (const float*)d_in[0];
    const int*   edge_feat= (const int*)  d_in[1];
    const int*   src      = (const int*)  d_in[2];
    const int*   dst      = (const int*)  d_in[3];
    const float* rel      = (const float*)d_in[4];
    const float* Wq       = (const float*)d_in[5];
    const float* bq       = (const float*)d_in[6];
    const float* Wk       = (const float*)d_in[7];
    const float* Wv       = (const float*)d_in[8];
    const float* Wo       = (const float*)d_in[9];
    const float* bo       = (const float*)d_in[10];
    const float* W1       = (const float*)d_in[11];
    const float* b1       = (const float*)d_in[12];
    const float* W2       = (const float*)d_in[13];
    const float* b2       = (const float*)d_in[14];
    const float* ln1g     = (const float*)d_in[15];
    const float* ln1b     = (const float*)d_in[16];
    const float* ln2g     = (const float*)d_in[17];
    const float* ln2b     = (const float*)d_in[18];

    float *q, *k, *v, *o, *tmp, *h, *xbuf, *ff;
    int* cnt;
    cudaGetSymbolAddress((void**)&q,    g_q);
    cudaGetSymbolAddress((void**)&k,    g_k);
    cudaGetSymbolAddress((void**)&v,    g_v);
    cudaGetSymbolAddress((void**)&o,    g_o);
    cudaGetSymbolAddress((void**)&tmp,  g_tmp);
    cudaGetSymbolAddress((void**)&h,    g_h);
    cudaGetSymbolAddress((void**)&xbuf, g_xbuf);
    cudaGetSymbolAddress((void**)&ff,   g_ff);
    cudaGetSymbolAddress((void**)&cnt,  g_cnt);

    cudaMemsetAsync(cnt, 0, N_NODES * sizeof(int));
    hist_kernel<<<(N_EDGES + 255) / 256, 256>>>(dst);
    scan_kernel<<<1, 1024>>>();
    scatter_kernel<<<(N_EDGES + 255) / 256, 256>>>(dst);

    const int warp_blocks = (N_NODES * 32 + 255) / 256;
    const int GM = (N_NODES + BM - 1) / BM;   // 157
    const int gnHS = HS / BN;                  // 2
    const int gnFF = FF_DIM / BN;              // 8
    const int tilesHS = GM * gnHS;             // 314
    const int tilesFF = GM * gnFF;             // 1256
    const int PGRID = 296;                     // 148 SMs x 2 CTAs

    const float* xin = x_in;
    for (int l = 0; l < N_LAYERS; l++) {
        const float* wq = Wq + (size_t)l * HS * HS;
        const float* wk = Wk + (size_t)l * HS * HS;
        const float* wv = Wv + (size_t)l * HS * HS;
        const float* wo = Wo + (size_t)l * HS * HS;
        const float* w1 = W1 + (size_t)l * HS * FF_DIM;
        const float* w2 = W2 + (size_t)l * FF_DIM * HS;

        bf16_gemm_qkv_kernel<<<PGRID, 256>>>(N_NODES, HS, HS, gnHS, tilesHS,
                                             xin, wq, wk, wv, bq + l * HS, q, k, v);

        edge_agg_kernel<<<warp_blocks, 256>>>(rel, edge_feat, src);

        bf16_gemm_kernel<2><<<PGRID, 256>>>(N_NODES, HS, HS, gnHS, tilesHS, o, wo, bo + l * HS, xin, tmp);
        ln_kernel<<<warp_blocks, 256>>>(tmp, ln1g + l * HS, ln1b + l * HS, h);

        bf16_gemm_kernel<1><<<PGRID, 256>>>(N_NODES, HS, FF_DIM, gnFF, tilesFF, h, w1, b1 + l * FF_DIM, nullptr, ff);
        bf16_gemm_kernel<2><<<PGRID, 256>>>(N_NODES, FF_DIM, HS, gnHS, tilesHS, ff, w2, b2 + l * HS, h, tmp);

        float* xnext = (l == N_LAYERS - 1) ? (float*)d_out : xbuf;
        ln_kernel<<<warp_blocks, 256>>>(tmp, ln2g + l * HS, ln2b + l * HS, xnext);
        xin = xbuf;
    }
}

// round 9
// speedup vs baseline: 3.4780x; 1.0573x over previous
#include <cuda_runtime.h>
#include <cuda_bf16.h>
#include <cstdint>

#define N_NODES 20000
#define N_EDGES 640000
#define HS 256
#define H_HEADS 8
#define DK 32
#define FF_DIM 1024
#define N_LAYERS 2

// ---------------- scratch (static device globals; no runtime alloc) ----------------
__device__ float g_q[(size_t)N_NODES * HS];
__device__ float g_k[(size_t)N_NODES * HS];
__device__ float g_v[(size_t)N_NODES * HS];
__device__ float g_tmp[(size_t)N_NODES * HS];
__device__ float g_h[(size_t)N_NODES * HS];
__device__ float g_xbuf[(size_t)N_NODES * HS];

// bf16 pair-word buffers (lo = even index, hi = odd index)
__device__ uint32_t g_xbf[(size_t)N_NODES * HS / 2];
__device__ uint32_t g_obf[(size_t)N_NODES * HS / 2];
__device__ uint32_t g_hbf[(size_t)N_NODES * HS / 2];
__device__ uint32_t g_ffbf[(size_t)N_NODES * FF_DIM / 2];

// interleaved bf16 weights: word[p][n] = {W[2p][n], W[2p+1][n]}
#define WQ_OFF 0
#define WK_OFF 32768
#define WV_OFF 65536
#define WO_OFF 98304
#define W1_OFF 131072
#define W2_OFF 262144
#define WL_STRIDE 393216
__device__ uint32_t g_wbf[2 * WL_STRIDE];

__device__ int g_cnt[N_NODES];
__device__ int g_rowptr[N_NODES + 1];
__device__ int g_cursor[N_NODES];
__device__ int g_eids[N_EDGES];

__device__ __forceinline__ uint32_t packbf2(float lo, float hi) {
    __nv_bfloat162 h = __float22bfloat162_rn(make_float2(lo, hi));
    return *reinterpret_cast<uint32_t*>(&h);
}

// ---------------- operand conversion ----------------
__global__ void convert_weights_kernel(const float* __restrict__ Wq, const float* __restrict__ Wk,
                                       const float* __restrict__ Wv, const float* __restrict__ Wo,
                                       const float* __restrict__ W1, const float* __restrict__ W2) {
    int w = blockIdx.x * blockDim.x + threadIdx.x;
    if (w >= 2 * WL_STRIDE) return;
    int layer = w / WL_STRIDE;
    int r = w % WL_STRIDE;
    const float* src;
    int Nc;
    if (r < W1_OFF) {
        int m = r >> 15; r &= 32767; Nc = HS;
        src = (m == 0 ? Wq : m == 1 ? Wk : m == 2 ? Wv : Wo) + (size_t)layer * HS * HS;
    } else if (r < W2_OFF) {
        r -= W1_OFF; Nc = FF_DIM; src = W1 + (size_t)layer * HS * FF_DIM;
    } else {
        r -= W2_OFF; Nc = HS; src = W2 + (size_t)layer * FF_DIM * HS;
    }
    int p = r / Nc, n = r % Nc;
    g_wbf[w] = packbf2(src[(size_t)(2 * p) * Nc + n], src[(size_t)(2 * p + 1) * Nc + n]);
}

__global__ void convert_x_kernel(const float* __restrict__ x) {
    int i = blockIdx.x * blockDim.x + threadIdx.x;
    if (i < N_NODES * HS / 2) g_xbf[i] = packbf2(x[2 * i], x[2 * i + 1]);
}

// ---------------- CSR build ----------------
__global__ void hist_kernel(const int* __restrict__ dst) {
    int i = blockIdx.x * blockDim.x + threadIdx.x;
    if (i < N_EDGES) atomicAdd(&g_cnt[dst[i]], 1);
}

__global__ void scan_kernel() {
    __shared__ int sh[1024];
    __shared__ int carry_sh;
    if (threadIdx.x == 0) carry_sh = 0;
    __syncthreads();
    for (int base = 0; base < N_NODES; base += 1024) {
        int i = base + threadIdx.x;
        int v = (i < N_NODES) ? g_cnt[i] : 0;
        sh[threadIdx.x] = v;
        __syncthreads();
        #pragma unroll
        for (int off = 1; off < 1024; off <<= 1) {
            int t = (threadIdx.x >= off) ? sh[threadIdx.x - off] : 0;
            __syncthreads();
            sh[threadIdx.x] += t;
            __syncthreads();
        }
        int incl = sh[threadIdx.x];
        int excl = incl - v + carry_sh;
        if (i < N_NODES) {
            g_rowptr[i] = excl;
            g_cursor[i] = excl;
        }
        __syncthreads();
        if (threadIdx.x == 1023) carry_sh += sh[1023];
        __syncthreads();
    }
    if (threadIdx.x == 0) g_rowptr[N_NODES] = carry_sh;
}

__global__ void scatter_kernel(const int* __restrict__ dst) {
    int i = blockIdx.x * blockDim.x + threadIdx.x;
    if (i < N_EDGES) {
        int p = atomicAdd(&g_cursor[dst[i]], 1);
        g_eids[p] = i;
    }
}

// ---------------- BF16 tensor-core GEMM (persistent CTAs, bf16 operands) ----------------
// A: bf16 pair-words [m][K/2]; B: interleaved bf16 pair-words [K/2][Nc].
// MODE 0: +bias (nullable)   MODE 1: relu(+bias)   MODE 2: +bias +res
#define BM 128
#define BN 128
#define KW 16               // pair-words per chunk (32 k-elements)
#define SPAD 8
#define SSTRIDE (BM + SPAD)

__device__ __forceinline__ void mma_bf16(float4& c, const uint32_t a[4], const uint32_t b[2]) {
    asm volatile(
        "mma.sync.aligned.m16n8k16.row.col.f32.bf16.bf16.f32 "
        "{%0,%1,%2,%3}, {%4,%5,%6,%7}, {%8,%9}, {%0,%1,%2,%3};"
        : "+f"(c.x), "+f"(c.y), "+f"(c.z), "+f"(c.w)
        : "r"(a[0]), "r"(a[1]), "r"(a[2]), "r"(a[3]), "r"(b[0]), "r"(b[1]));
}

typedef uint32_t SmemBuf[2][KW][SSTRIDE];

template <int MODE, bool OUTBF>
__device__ __forceinline__ void gemm_tile(
    SmemBuf& As, SmemBuf& Bs,
    int M, int K, int Nc, int m0, int n0,
    const uint32_t* __restrict__ Aw,      // [m][K/2] pair-words
    const uint32_t* __restrict__ Bw,      // [K/2][Nc] pair-words
    const float* __restrict__ bias,
    const float* __restrict__ res,
    float* __restrict__ C,
    uint32_t* __restrict__ Cbf)
{
    const int tid  = threadIdx.x;
    const int lane = tid & 31;
    const int warp = tid >> 5;
    const int g  = lane >> 2;
    const int tg = lane & 3;
    const int wm = (warp >> 2) * 64;
    const int wn = (warp & 3) * 32;

    const int Khalf = K >> 1;
    // A fill: row = tid>>1 (0..127), w0 = (tid&1)*8 ; 8 words (2x uint4) per thread per chunk
    const int a_row = tid >> 1;
    const int a_w0  = (tid & 1) * 8;
    // B fill: idx = tid + 256*i -> p = idx>>5 (0..15), n4 = (idx&31)*4 ; uint4 per slot
    const int b_p   = tid >> 5;
    const int b_n4  = (tid & 31) * 4;

    const int nch = K >> 5;

    float4 acc[4][4];
    #pragma unroll
    for (int i = 0; i < 4; i++)
        #pragma unroll
        for (int j = 0; j < 4; j++) acc[i][j] = make_float4(0.f, 0.f, 0.f, 0.f);

    uint4 aU0, aU1, bU0, bU1;

    // ---- prime chunk 0 into buffer 0 ----
    {
        aU0 = make_uint4(0, 0, 0, 0); aU1 = make_uint4(0, 0, 0, 0);
        if (m0 + a_row < M) {
            const uint4* ap = (const uint4*)(Aw + (size_t)(m0 + a_row) * Khalf + a_w0);
            aU0 = ap[0]; aU1 = ap[1];
        }
        As[0][a_w0 + 0][a_row] = aU0.x; As[0][a_w0 + 1][a_row] = aU0.y;
        As[0][a_w0 + 2][a_row] = aU0.z; As[0][a_w0 + 3][a_row] = aU0.w;
        As[0][a_w0 + 4][a_row] = aU1.x; As[0][a_w0 + 5][a_row] = aU1.y;
        As[0][a_w0 + 6][a_row] = aU1.z; As[0][a_w0 + 7][a_row] = aU1.w;
        bU0 = *(const uint4*)(Bw + (size_t)b_p * Nc + n0 + b_n4);
        bU1 = *(const uint4*)(Bw + (size_t)(b_p + 8) * Nc + n0 + b_n4);
        *(uint4*)(&Bs[0][b_p][b_n4])     = bU0;
        *(uint4*)(&Bs[0][b_p + 8][b_n4]) = bU1;
    }
    __syncthreads();

    for (int ch = 0; ch < nch; ch++) {
        const int cur = ch & 1;
        const int nxt = cur ^ 1;
        const bool has_next = (ch + 1 < nch);

        if (has_next) {
            const int kw0 = (ch + 1) * KW;
            aU0 = make_uint4(0, 0, 0, 0); aU1 = make_uint4(0, 0, 0, 0);
            if (m0 + a_row < M) {
                const uint4* ap = (const uint4*)(Aw + (size_t)(m0 + a_row) * Khalf + kw0 + a_w0);
                aU0 = ap[0]; aU1 = ap[1];
            }
            bU0 = *(const uint4*)(Bw + (size_t)(kw0 + b_p) * Nc + n0 + b_n4);
            bU1 = *(const uint4*)(Bw + (size_t)(kw0 + b_p + 8) * Nc + n0 + b_n4);
        }

        #pragma unroll
        for (int ks = 0; ks < KW; ks += 8) {
            uint32_t afr[4][4];
            uint32_t bfr[4][2];
            #pragma unroll
            for (int mt = 0; mt < 4; mt++) {
                const int m = wm + mt * 16 + g;
                afr[mt][0] = As[cur][ks + tg][m];
                afr[mt][1] = As[cur][ks + tg][m + 8];
                afr[mt][2] = As[cur][ks + tg + 4][m];
                afr[mt][3] = As[cur][ks + tg + 4][m + 8];
            }
            #pragma unroll
            for (int nt = 0; nt < 4; nt++) {
                const int n = wn + nt * 8 + g;
                bfr[nt][0] = Bs[cur][ks + tg][n];
                bfr[nt][1] = Bs[cur][ks + tg + 4][n];
            }
            #pragma unroll
            for (int mt = 0; mt < 4; mt++)
                #pragma unroll
                for (int nt = 0; nt < 4; nt++)
                    mma_bf16(acc[mt][nt], afr[mt], bfr[nt]);
        }

        if (has_next) {
            As[nxt][a_w0 + 0][a_row] = aU0.x; As[nxt][a_w0 + 1][a_row] = aU0.y;
            As[nxt][a_w0 + 2][a_row] = aU0.z; As[nxt][a_w0 + 3][a_row] = aU0.w;
            As[nxt][a_w0 + 4][a_row] = aU1.x; As[nxt][a_w0 + 5][a_row] = aU1.y;
            As[nxt][a_w0 + 6][a_row] = aU1.z; As[nxt][a_w0 + 7][a_row] = aU1.w;
            *(uint4*)(&Bs[nxt][b_p][b_n4])     = bU0;
            *(uint4*)(&Bs[nxt][b_p + 8][b_n4]) = bU1;
            __syncthreads();
        }
    }

    // ---- epilogue ----
    #pragma unroll
    for (int mt = 0; mt < 4; mt++) {
        #pragma unroll
        for (int nt = 0; nt < 4; nt++) {
            const int row0 = m0 + wm + mt * 16 + g;
            const int row1 = row0 + 8;
            const int col  = n0 + wn + nt * 8 + tg * 2;
            float2 v0 = make_float2(acc[mt][nt].x, acc[mt][nt].y);
            float2 v1 = make_float2(acc[mt][nt].z, acc[mt][nt].w);
            if (bias) {
                float2 bb = *(const float2*)(bias + col);
                v0.x += bb.x; v0.y += bb.y;
                v1.x += bb.x; v1.y += bb.y;
            }
            if (MODE == 2) {
                if (row0 < M) {
                    float2 r0 = *(const float2*)(res + (size_t)row0 * Nc + col);
                    v0.x += r0.x; v0.y += r0.y;
                }
                if (row1 < M) {
                    float2 r1 = *(const float2*)(res + (size_t)row1 * Nc + col);
                    v1.x += r1.x; v1.y += r1.y;
                }
            }
            if (MODE == 1) {
                v0.x = fmaxf(v0.x, 0.f); v0.y = fmaxf(v0.y, 0.f);
                v1.x = fmaxf(v1.x, 0.f); v1.y = fmaxf(v1.y, 0.f);
            }
            if (OUTBF) {
                if (row0 < M) Cbf[(size_t)row0 * (Nc >> 1) + (col >> 1)] = packbf2(v0.x, v0.y);
                if (row1 < M) Cbf[(size_t)row1 * (Nc >> 1) + (col >> 1)] = packbf2(v1.x, v1.y);
            } else {
                if (row0 < M) *(float2*)(C + (size_t)row0 * Nc + col) = v0;
                if (row1 < M) *(float2*)(C + (size_t)row1 * Nc + col) = v1;
            }
        }
    }
}

template <int MODE, bool OUTBF>
__global__ __launch_bounds__(256, 2) void bf16_gemm_kernel(
    int M, int K, int Nc, int gn, int total_tiles,
    const uint32_t* __restrict__ Aw,
    const uint32_t* __restrict__ Bw,
    const float* __restrict__ bias,
    const float* __restrict__ res,
    float* __restrict__ C,
    uint32_t* __restrict__ Cbf)
{
    __shared__ SmemBuf As;
    __shared__ SmemBuf Bs;
    for (int t = blockIdx.x; t < total_tiles; t += gridDim.x) {
        const int m0 = (t / gn) * BM;
        const int n0 = (t % gn) * BN;
        __syncthreads();
        gemm_tile<MODE, OUTBF>(As, Bs, M, K, Nc, m0, n0, Aw, Bw, bias, res, C, Cbf);
    }
}

// fused q/k/v: three GEMMs sharing A, one persistent launch
__global__ __launch_bounds__(256, 2) void bf16_gemm_qkv_kernel(
    int M, int K, int Nc, int gn, int tiles_per,
    const uint32_t* __restrict__ Aw,
    const uint32_t* __restrict__ Bq,
    const uint32_t* __restrict__ Bk,
    const uint32_t* __restrict__ Bv,
    const float* __restrict__ biasq,
    float* __restrict__ Cq,
    float* __restrict__ Ck,
    float* __restrict__ Cv)
{
    __shared__ SmemBuf As;
    __shared__ SmemBuf Bs;
    const int total = 3 * tiles_per;
    for (int t = blockIdx.x; t < total; t += gridDim.x) {
        const int which = t / tiles_per;
        const int tt = t % tiles_per;
        const int m0 = (tt / gn) * BM;
        const int n0 = (tt % gn) * BN;
        const uint32_t* B = (which == 0) ? Bq : (which == 1) ? Bk : Bv;
        float* C          = (which == 0) ? Cq : (which == 1) ? Ck : Cv;
        const float* bias = (which == 0) ? biasq : nullptr;
        __syncthreads();
        gemm_tile<0, false>(As, Bs, M, K, Nc, m0, n0, Aw, B, bias, nullptr, C, nullptr);
    }
}

// ---------------- edge aggregation: one warp per destination node ----------------
__global__ void edge_agg_kernel(const float* __restrict__ rel,
                                const int* __restrict__ edge_feat,
                                const int* __restrict__ src)
{
    int gw = (blockIdx.x * blockDim.x + threadIdx.x) >> 5;
    int lane = threadIdx.x & 31;
    if (gw >= N_NODES) return;

    const float4* qr = (const float4*)(g_q + (size_t)gw * HS);
    float4 q0 = qr[2 * lane], q1 = qr[2 * lane + 1];

    float4 a0 = make_float4(0.f, 0.f, 0.f, 0.f);
    float4 a1 = make_float4(0.f, 0.f, 0.f, 0.f);
    float zsum = 0.f;

    const int beg = g_rowptr[gw], end = g_rowptr[gw + 1];
    const int ecol = 2 * (lane & 3);
    const float invs = 0.17677669529663687f;  // 1/sqrt(32)

    for (int base = beg; base < end; base += 32) {
        const int cnt = min(32, end - base);
        int s_l = 0, r_l = 0;
        if (base + lane < end) {
            int e = g_eids[base + lane];
            s_l = __ldg(&src[e]);
            r_l = __ldg(&edge_feat[e]);
        }

        int s_c = __shfl_sync(0xffffffffu, s_l, 0);
        int r_c = __shfl_sync(0xffffffffu, r_l, 0);
        const float4* kr = (const float4*)(g_k + (size_t)s_c * HS);
        const float4* vr = (const float4*)(g_v + (size_t)s_c * HS);
        const float4* er = (const float4*)(rel + (size_t)r_c * DK);
        float4 k0 = kr[2 * lane], k1 = kr[2 * lane + 1];
        float4 v0 = vr[2 * lane], v1 = vr[2 * lane + 1];
        float4 e0 = er[ecol],     e1 = er[ecol + 1];

        for (int j = 0; j < cnt; j++) {
            float4 K0 = k0, K1 = k1, V0 = v0, V1 = v1, E0 = e0, E1 = e1;
            if (j + 1 < cnt) {
                int s_n = __shfl_sync(0xffffffffu, s_l, j + 1);
                int r_n = __shfl_sync(0xffffffffu, r_l, j + 1);
                const float4* krn = (const float4*)(g_k + (size_t)s_n * HS);
                const float4* vrn = (const float4*)(g_v + (size_t)s_n * HS);
                const float4* ern = (const float4*)(rel + (size_t)r_n * DK);
                k0 = krn[2 * lane]; k1 = krn[2 * lane + 1];
                v0 = vrn[2 * lane]; v1 = vrn[2 * lane + 1];
                e0 = ern[ecol];     e1 = ern[ecol + 1];
            }

            float d = (K0.x + E0.x) * q0.x + (K0.y + E0.y) * q0.y
                    + (K0.z + E0.z) * q0.z + (K0.w + E0.w) * q0.w
                    + (K1.x + E1.x) * q1.x + (K1.y + E1.y) * q1.y
                    + (K1.z + E1.z) * q1.z + (K1.w + E1.w) * q1.w;
            d += __shfl_xor_sync(0xffffffffu, d, 1);
            d += __shfl_xor_sync(0xffffffffu, d, 2);
            float sc = __expf(fminf(fmaxf(d * invs, -10.f), 10.f));

            a0.x += (V0.x + E0.x) * sc; a0.y += (V0.y + E0.y) * sc;
            a0.z += (V0.z + E0.z) * sc; a0.w += (V0.w + E0.w) * sc;
            a1.x += (V1.x + E1.x) * sc; a1.y += (V1.y + E1.y) * sc;
            a1.z += (V1.z + E1.z) * sc; a1.w += (V1.w + E1.w) * sc;
            zsum += sc;
        }
    }

    float inv = 1.f / zsum;
    // write bf16 pair-words directly (o feeds only the Wo GEMM)
    uint4 w;
    w.x = packbf2(a0.x * inv, a0.y * inv);
    w.y = packbf2(a0.z * inv, a0.w * inv);
    w.z = packbf2(a1.x * inv, a1.y * inv);
    w.w = packbf2(a1.z * inv, a1.w * inv);
    *(uint4*)(g_obf + (size_t)gw * (HS / 2) + 4 * lane) = w;
}

// ---------------- layernorm: one warp per row; optional bf16 dual-write ----------------
__global__ void ln_kernel(const float* __restrict__ in,
                          const float* __restrict__ gamma,
                          const float* __restrict__ beta,
                          float* __restrict__ out,
                          uint32_t* __restrict__ outbf)
{
    int gw = (blockIdx.x * blockDim.x + threadIdx.x) >> 5;
    int lane = threadIdx.x & 31;
    if (gw >= N_NODES) return;

    const float4* row = (const float4*)(in + (size_t)gw * HS);
    float4 x0 = row[2 * lane], x1 = row[2 * lane + 1];

    float s = x0.x + x0.y + x0.z + x0.w + x1.x + x1.y + x1.z + x1.w;
    #pragma unroll
    for (int off = 16; off; off >>= 1) s += __shfl_xor_sync(0xffffffffu, s, off);
    float mean = s * (1.f / HS);

    float d0 = x0.x - mean, d1 = x0.y - mean, d2 = x0.z - mean, d3 = x0.w - mean;
    float d4 = x1.x - mean, d5 = x1.y - mean, d6 = x1.z - mean, d7 = x1.w - mean;
    float ss = d0 * d0 + d1 * d1 + d2 * d2 + d3 * d3 + d4 * d4 + d5 * d5 + d6 * d6 + d7 * d7;
    #pragma unroll
    for (int off = 16; off; off >>= 1) ss += __shfl_xor_sync(0xffffffffu, ss, off);
    float rstd = rsqrtf(ss * (1.f / HS) + 1e-5f);

    const float4* gr = (const float4*)gamma;
    const float4* br = (const float4*)beta;
    float4 gg0 = gr[2 * lane], gg1 = gr[2 * lane + 1];
    float4 bb0 = br[2 * lane], bb1 = br[2 * lane + 1];

    float o0 = d0 * rstd * gg0.x + bb0.x;
    float o1 = d1 * rstd * gg0.y + bb0.y;
    float o2 = d2 * rstd * gg0.z + bb0.z;
    float o3 = d3 * rstd * gg0.w + bb0.w;
    float o4 = d4 * rstd * gg1.x + bb1.x;
    float o5 = d5 * rstd * gg1.y + bb1.y;
    float o6 = d6 * rstd * gg1.z + bb1.z;
    float o7 = d7 * rstd * gg1.w + bb1.w;

    float4* orow = (float4*)(out + (size_t)gw * HS);
    orow[2 * lane]     = make_float4(o0, o1, o2, o3);
    orow[2 * lane + 1] = make_float4(o4, o5, o6, o7);

    if (outbf) {
        uint4 w;
        w.x = packbf2(o0, o1); w.y = packbf2(o2, o3);
        w.z = packbf2(o4, o5); w.w = packbf2(o6, o7);
        *(uint4*)(outbf + (size_t)gw * (HS / 2) + 4 * lane) = w;
    }
}

// ---------------- host orchestration ----------------
extern "C" void kernel_launch(void* const* d_in, const int* in_sizes, int n_in,
                              void* d_out, int out_size)
{
    const float* x_in     = (const float*)d_in[0];
    const int*   edge_feat= (const int*)  d_in[1];
    const int*   src      = (const int*)  d_in[2];
    const int*   dst      = (const int*)  d_in[3];
    const float* rel      = (const float*)d_in[4];
    const float* Wq       = (const float*)d_in[5];
    const float* bq       = (const float*)d_in[6];
    const float* Wk       = (const float*)d_in[7];
    const float* Wv       = (const float*)d_in[8];
    const float* Wo       = (const float*)d_in[9];
    const float* bo       = (const float*)d_in[10];
    const float* W1       = (const float*)d_in[11];
    const float* b1       = (const float*)d_in[12];
    const float* W2       = (const float*)d_in[13];
    const float* b2       = (const float*)d_in[14];
    const float* ln1g     = (const float*)d_in[15];
    const float* ln1b     = (const float*)d_in[16];
    const float* ln2g     = (const float*)d_in[17];
    const float* ln2b     = (const float*)d_in[18];

    float *q, *k, *v, *tmp, *h, *xbuf;
    uint32_t *xbf, *obf, *hbf, *ffbf, *wbf;
    int* cnt;
    cudaGetSymbolAddress((void**)&q,    g_q);
    cudaGetSymbolAddress((void**)&k,    g_k);
    cudaGetSymbolAddress((void**)&v,    g_v);
    cudaGetSymbolAddress((void**)&tmp,  g_tmp);
    cudaGetSymbolAddress((void**)&h,    g_h);
    cudaGetSymbolAddress((void**)&xbuf, g_xbuf);
    cudaGetSymbolAddress((void**)&xbf,  g_xbf);
    cudaGetSymbolAddress((void**)&obf,  g_obf);
    cudaGetSymbolAddress((void**)&hbf,  g_hbf);
    cudaGetSymbolAddress((void**)&ffbf, g_ffbf);
    cudaGetSymbolAddress((void**)&wbf,  g_wbf);
    cudaGetSymbolAddress((void**)&cnt,  g_cnt);

    // operand conversion (graph-capturable kernels)
    convert_weights_kernel<<<(2 * WL_STRIDE + 255) / 256, 256>>>(Wq, Wk, Wv, Wo, W1, W2);
    convert_x_kernel<<<(N_NODES * HS / 2 + 255) / 256, 256>>>(x_in);

    // CSR by dst
    cudaMemsetAsync(cnt, 0, N_NODES * sizeof(int));
    hist_kernel<<<(N_EDGES + 255) / 256, 256>>>(dst);
    scan_kernel<<<1, 1024>>>();
    scatter_kernel<<<(N_EDGES + 255) / 256, 256>>>(dst);

    const int warp_blocks = (N_NODES * 32 + 255) / 256;
    const int GM = (N_NODES + BM - 1) / BM;   // 157
    const int gnHS = HS / BN;                  // 2
    const int gnFF = FF_DIM / BN;              // 8
    const int tilesHS = GM * gnHS;             // 314
    const int tilesFF = GM * gnFF;             // 1256
    const int PGRID = 296;

    const float* xres = x_in;   // fp32 residual input for this layer
    for (int l = 0; l < N_LAYERS; l++) {
        const uint32_t* wl = wbf + (size_t)l * WL_STRIDE;

        bf16_gemm_qkv_kernel<<<PGRID, 256>>>(N_NODES, HS, HS, gnHS, tilesHS,
                                             xbf, wl + WQ_OFF, wl + WK_OFF, wl + WV_OFF,
                                             bq + l * HS, q, k, v);

        edge_agg_kernel<<<warp_blocks, 256>>>(rel, edge_feat, src);

        bf16_gemm_kernel<2, false><<<PGRID, 256>>>(N_NODES, HS, HS, gnHS, tilesHS,
                                                   obf, wl + WO_OFF, bo + l * HS, xres, tmp, nullptr);
        ln_kernel<<<warp_blocks, 256>>>(tmp, ln1g + l * HS, ln1b + l * HS, h, hbf);

        bf16_gemm_kernel<1, true><<<PGRID, 256>>>(N_NODES, HS, FF_DIM, gnFF, tilesFF,
                                                  hbf, wl + W1_OFF, b1 + l * FF_DIM, nullptr, nullptr, ffbf);
        bf16_gemm_kernel<2, false><<<PGRID, 256>>>(N_NODES, FF_DIM, HS, gnHS, tilesHS,
                                                   ffbf, wl + W2_OFF, b2 + l * HS, h, tmp, nullptr);

        if (l == N_LAYERS - 1) {
            ln_kernel<<<warp_blocks, 256>>>(tmp, ln2g + l * HS, ln2b + l * HS, (float*)d_out, nullptr);
        } else {
            ln_kernel<<<warp_blocks, 256>>>(tmp, ln2g + l * HS, ln2b + l * HS, xbuf, xbf);
            xres = xbuf;
        }
    }
}

// round 10
// speedup vs baseline: 3.7579x; 1.0805x over previous
#include <cuda_runtime.h>
#include <cuda_bf16.h>
#include <cstdint>

#define N_NODES 20000
#define N_EDGES 640000
#define HS 256
#define H_HEADS 8
#define DK 32
#define FF_DIM 1024
#define N_LAYERS 2

// ---------------- scratch (static device globals; no runtime alloc) ----------------
__device__ float g_q[(size_t)N_NODES * HS];
__device__ float g_k[(size_t)N_NODES * HS];
__device__ float g_tmp[(size_t)N_NODES * HS];
__device__ float g_h[(size_t)N_NODES * HS];
__device__ float g_xbuf[(size_t)N_NODES * HS];

// bf16 pair-word buffers (lo = even index, hi = odd index)
__device__ uint32_t g_xbf[(size_t)N_NODES * HS / 2];
__device__ uint32_t g_vbf[(size_t)N_NODES * HS / 2];
__device__ uint32_t g_obf[(size_t)N_NODES * HS / 2];
__device__ uint32_t g_hbf[(size_t)N_NODES * HS / 2];
__device__ uint32_t g_ffbf[(size_t)N_NODES * FF_DIM / 2];

// interleaved bf16 weights: word[p][n] = {W[2p][n], W[2p+1][n]}
#define WQ_OFF 0
#define WK_OFF 32768
#define WV_OFF 65536
#define WO_OFF 98304
#define W1_OFF 131072
#define W2_OFF 262144
#define WL_STRIDE 393216
__device__ uint32_t g_wbf[2 * WL_STRIDE];

__device__ int g_cnt[N_NODES];
__device__ int g_rowptr[N_NODES + 1];
__device__ int g_cursor[N_NODES];
__device__ int g_eids[N_EDGES];

__device__ __forceinline__ uint32_t packbf2(float lo, float hi) {
    __nv_bfloat162 h = __float22bfloat162_rn(make_float2(lo, hi));
    return *reinterpret_cast<uint32_t*>(&h);
}

__device__ __forceinline__ float2 unpackbf2(uint32_t w) {
    return __bfloat1622float2(*reinterpret_cast<__nv_bfloat162*>(&w));
}

// ---------------- operand conversion ----------------
__global__ void convert_weights_kernel(const float* __restrict__ Wq, const float* __restrict__ Wk,
                                       const float* __restrict__ Wv, const float* __restrict__ Wo,
                                       const float* __restrict__ W1, const float* __restrict__ W2) {
    int w = blockIdx.x * blockDim.x + threadIdx.x;
    if (w >= 2 * WL_STRIDE) return;
    int layer = w / WL_STRIDE;
    int r = w % WL_STRIDE;
    const float* src;
    int Nc;
    if (r < W1_OFF) {
        int m = r >> 15; r &= 32767; Nc = HS;
        src = (m == 0 ? Wq : m == 1 ? Wk : m == 2 ? Wv : Wo) + (size_t)layer * HS * HS;
    } else if (r < W2_OFF) {
        r -= W1_OFF; Nc = FF_DIM; src = W1 + (size_t)layer * HS * FF_DIM;
    } else {
        r -= W2_OFF; Nc = HS; src = W2 + (size_t)layer * FF_DIM * HS;
    }
    int p = r / Nc, n = r % Nc;
    g_wbf[w] = packbf2(src[(size_t)(2 * p) * Nc + n], src[(size_t)(2 * p + 1) * Nc + n]);
}

__global__ void convert_x_kernel(const float* __restrict__ x) {
    int i = blockIdx.x * blockDim.x + threadIdx.x;
    if (i < N_NODES * HS / 2) g_xbf[i] = packbf2(x[2 * i], x[2 * i + 1]);
}

// ---------------- CSR build ----------------
__global__ void hist_kernel(const int* __restrict__ dst) {
    int i = blockIdx.x * blockDim.x + threadIdx.x;
    if (i < N_EDGES) atomicAdd(&g_cnt[dst[i]], 1);
}

// single-block scan, warp-shuffle based (3 barriers per 1024 chunk)
__global__ void scan_kernel() {
    __shared__ int wsum[32];
    __shared__ int woff[32];
    __shared__ int total_sh;
    __shared__ int carry;
    const int tid = threadIdx.x, lane = tid & 31, wid = tid >> 5;
    if (tid == 0) carry = 0;
    __syncthreads();
    for (int base = 0; base < N_NODES; base += 1024) {
        int i = base + tid;
        int v = (i < N_NODES) ? g_cnt[i] : 0;
        int incl = v;
        #pragma unroll
        for (int off = 1; off < 32; off <<= 1) {
            int t = __shfl_up_sync(0xffffffffu, incl, off);
            if (lane >= off) incl += t;
        }
        if (lane == 31) wsum[wid] = incl;
        __syncthreads();                       // (A)
        if (wid == 0) {
            int s = wsum[lane];
            int si = s;
            #pragma unroll
            for (int off = 1; off < 32; off <<= 1) {
                int t = __shfl_up_sync(0xffffffffu, si, off);
                if (lane >= off) si += t;
            }
            woff[lane] = si - s;
            if (lane == 31) total_sh = si;
        }
        __syncthreads();                       // (B)
        int excl = incl - v + woff[wid] + carry;
        if (i < N_NODES) {
            g_rowptr[i] = excl;
            g_cursor[i] = excl;
        }
        __syncthreads();                       // (C)
        if (tid == 0) carry += total_sh;
    }
    if (tid == 0) g_rowptr[N_NODES] = carry;
}

__global__ void scatter_kernel(const int* __restrict__ dst) {
    int i = blockIdx.x * blockDim.x + threadIdx.x;
    if (i < N_EDGES) {
        int p = atomicAdd(&g_cursor[dst[i]], 1);
        g_eids[p] = i;
    }
}

// ---------------- BF16 tensor-core GEMM (persistent CTAs, bf16 operands) ----------------
#define BM 128
#define BN 128
#define KW 16
#define SPAD 8
#define SSTRIDE (BM + SPAD)

__device__ __forceinline__ void mma_bf16(float4& c, const uint32_t a[4], const uint32_t b[2]) {
    asm volatile(
        "mma.sync.aligned.m16n8k16.row.col.f32.bf16.bf16.f32 "
        "{%0,%1,%2,%3}, {%4,%5,%6,%7}, {%8,%9}, {%0,%1,%2,%3};"
        : "+f"(c.x), "+f"(c.y), "+f"(c.z), "+f"(c.w)
        : "r"(a[0]), "r"(a[1]), "r"(a[2]), "r"(a[3]), "r"(b[0]), "r"(b[1]));
}

typedef uint32_t SmemBuf[2][KW][SSTRIDE];

template <int MODE, bool OUTBF>
__device__ __forceinline__ void gemm_tile(
    SmemBuf& As, SmemBuf& Bs,
    int M, int K, int Nc, int m0, int n0,
    const uint32_t* __restrict__ Aw,
    const uint32_t* __restrict__ Bw,
    const float* __restrict__ bias,
    const float* __restrict__ res,
    float* __restrict__ C,
    uint32_t* __restrict__ Cbf)
{
    const int tid  = threadIdx.x;
    const int lane = tid & 31;
    const int warp = tid >> 5;
    const int g  = lane >> 2;
    const int tg = lane & 3;
    const int wm = (warp >> 2) * 64;
    const int wn = (warp & 3) * 32;

    const int Khalf = K >> 1;
    const int a_row = tid >> 1;
    const int a_w0  = (tid & 1) * 8;
    const int b_p   = tid >> 5;
    const int b_n4  = (tid & 31) * 4;

    const int nch = K >> 5;

    float4 acc[4][4];
    #pragma unroll
    for (int i = 0; i < 4; i++)
        #pragma unroll
        for (int j = 0; j < 4; j++) acc[i][j] = make_float4(0.f, 0.f, 0.f, 0.f);

    uint4 aU0, aU1, bU0, bU1;

    {
        aU0 = make_uint4(0, 0, 0, 0); aU1 = make_uint4(0, 0, 0, 0);
        if (m0 + a_row < M) {
            const uint4* ap = (const uint4*)(Aw + (size_t)(m0 + a_row) * Khalf + a_w0);
            aU0 = ap[0]; aU1 = ap[1];
        }
        As[0][a_w0 + 0][a_row] = aU0.x; As[0][a_w0 + 1][a_row] = aU0.y;
        As[0][a_w0 + 2][a_row] = aU0.z; As[0][a_w0 + 3][a_row] = aU0.w;
        As[0][a_w0 + 4][a_row] = aU1.x; As[0][a_w0 + 5][a_row] = aU1.y;
        As[0][a_w0 + 6][a_row] = aU1.z; As[0][a_w0 + 7][a_row] = aU1.w;
        bU0 = *(const uint4*)(Bw + (size_t)b_p * Nc + n0 + b_n4);
        bU1 = *(const uint4*)(Bw + (size_t)(b_p + 8) * Nc + n0 + b_n4);
        *(uint4*)(&Bs[0][b_p][b_n4])     = bU0;
        *(uint4*)(&Bs[0][b_p + 8][b_n4]) = bU1;
    }
    __syncthreads();

    for (int ch = 0; ch < nch; ch++) {
        const int cur = ch & 1;
        const int nxt = cur ^ 1;
        const bool has_next = (ch + 1 < nch);

        if (has_next) {
            const int kw0 = (ch + 1) * KW;
            aU0 = make_uint4(0, 0, 0, 0); aU1 = make_uint4(0, 0, 0, 0);
            if (m0 + a_row < M) {
                const uint4* ap = (const uint4*)(Aw + (size_t)(m0 + a_row) * Khalf + kw0 + a_w0);
                aU0 = ap[0]; aU1 = ap[1];
            }
            bU0 = *(const uint4*)(Bw + (size_t)(kw0 + b_p) * Nc + n0 + b_n4);
            bU1 = *(const uint4*)(Bw + (size_t)(kw0 + b_p + 8) * Nc + n0 + b_n4);
        }

        #pragma unroll
        for (int ks = 0; ks < KW; ks += 8) {
            uint32_t afr[4][4];
            uint32_t bfr[4][2];
            #pragma unroll
            for (int mt = 0; mt < 4; mt++) {
                const int m = wm + mt * 16 + g;
                afr[mt][0] = As[cur][ks + tg][m];
                afr[mt][1] = As[cur][ks + tg][m + 8];
                afr[mt][2] = As[cur][ks + tg + 4][m];
                afr[mt][3] = As[cur][ks + tg + 4][m + 8];
            }
            #pragma unroll
            for (int nt = 0; nt < 4; nt++) {
                const int n = wn + nt * 8 + g;
                bfr[nt][0] = Bs[cur][ks + tg][n];
                bfr[nt][1] = Bs[cur][ks + tg + 4][n];
            }
            #pragma unroll
            for (int mt = 0; mt < 4; mt++)
                #pragma unroll
                for (int nt = 0; nt < 4; nt++)
                    mma_bf16(acc[mt][nt], afr[mt], bfr[nt]);
        }

        if (has_next) {
            As[nxt][a_w0 + 0][a_row] = aU0.x; As[nxt][a_w0 + 1][a_row] = aU0.y;
            As[nxt][a_w0 + 2][a_row] = aU0.z; As[nxt][a_w0 + 3][a_row] = aU0.w;
            As[nxt][a_w0 + 4][a_row] = aU1.x; As[nxt][a_w0 + 5][a_row] = aU1.y;
            As[nxt][a_w0 + 6][a_row] = aU1.z; As[nxt][a_w0 + 7][a_row] = aU1.w;
            *(uint4*)(&Bs[nxt][b_p][b_n4])     = bU0;
            *(uint4*)(&Bs[nxt][b_p + 8][b_n4]) = bU1;
            __syncthreads();
        }
    }

    #pragma unroll
    for (int mt = 0; mt < 4; mt++) {
        #pragma unroll
        for (int nt = 0; nt < 4; nt++) {
            const int row0 = m0 + wm + mt * 16 + g;
            const int row1 = row0 + 8;
            const int col  = n0 + wn + nt * 8 + tg * 2;
            float2 v0 = make_float2(acc[mt][nt].x, acc[mt][nt].y);
            float2 v1 = make_float2(acc[mt][nt].z, acc[mt][nt].w);
            if (bias) {
                float2 bb = *(const float2*)(bias + col);
                v0.x += bb.x; v0.y += bb.y;
                v1.x += bb.x; v1.y += bb.y;
            }
            if (MODE == 2) {
                if (row0 < M) {
                    float2 r0 = *(const float2*)(res + (size_t)row0 * Nc + col);
                    v0.x += r0.x; v0.y += r0.y;
                }
                if (row1 < M) {
                    float2 r1 = *(const float2*)(res + (size_t)row1 * Nc + col);
                    v1.x += r1.x; v1.y += r1.y;
                }
            }
            if (MODE == 1) {
                v0.x = fmaxf(v0.x, 0.f); v0.y = fmaxf(v0.y, 0.f);
                v1.x = fmaxf(v1.x, 0.f); v1.y = fmaxf(v1.y, 0.f);
            }
            if (OUTBF) {
                if (row0 < M) Cbf[(size_t)row0 * (Nc >> 1) + (col >> 1)] = packbf2(v0.x, v0.y);
                if (row1 < M) Cbf[(size_t)row1 * (Nc >> 1) + (col >> 1)] = packbf2(v1.x, v1.y);
            } else {
                if (row0 < M) *(float2*)(C + (size_t)row0 * Nc + col) = v0;
                if (row1 < M) *(float2*)(C + (size_t)row1 * Nc + col) = v1;
            }
        }
    }
}

template <int MODE, bool OUTBF>
__global__ __launch_bounds__(256, 2) void bf16_gemm_kernel(
    int M, int K, int Nc, int gn, int total_tiles,
    const uint32_t* __restrict__ Aw,
    const uint32_t* __restrict__ Bw,
    const float* __restrict__ bias,
    const float* __restrict__ res,
    float* __restrict__ C,
    uint32_t* __restrict__ Cbf)
{
    __shared__ SmemBuf As;
    __shared__ SmemBuf Bs;
    for (int t = blockIdx.x; t < total_tiles; t += gridDim.x) {
        const int m0 = (t / gn) * BM;
        const int n0 = (t % gn) * BN;
        __syncthreads();
        gemm_tile<MODE, OUTBF>(As, Bs, M, K, Nc, m0, n0, Aw, Bw, bias, res, C, Cbf);
    }
}

// fused q/k/v: q,k -> fp32 ; v -> bf16 pair-words
__global__ __launch_bounds__(256, 2) void bf16_gemm_qkv_kernel(
    int M, int K, int Nc, int gn, int tiles_per,
    const uint32_t* __restrict__ Aw,
    const uint32_t* __restrict__ Bq,
    const uint32_t* __restrict__ Bk,
    const uint32_t* __restrict__ Bv,
    const float* __restrict__ biasq,
    float* __restrict__ Cq,
    float* __restrict__ Ck,
    uint32_t* __restrict__ Cvbf)
{
    __shared__ SmemBuf As;
    __shared__ SmemBuf Bs;
    const int total = 3 * tiles_per;
    for (int t = blockIdx.x; t < total; t += gridDim.x) {
        const int which = t / tiles_per;
        const int tt = t % tiles_per;
        const int m0 = (tt / gn) * BM;
        const int n0 = (tt % gn) * BN;
        __syncthreads();
        if (which == 2) {
            gemm_tile<0, true>(As, Bs, M, K, Nc, m0, n0, Aw, Bv, nullptr, nullptr, nullptr, Cvbf);
        } else {
            const uint32_t* B = (which == 0) ? Bq : Bk;
            float* C          = (which == 0) ? Cq : Ck;
            const float* bias = (which == 0) ? biasq : nullptr;
            gemm_tile<0, false>(As, Bs, M, K, Nc, m0, n0, Aw, B, bias, nullptr, C, nullptr);
        }
    }
}

// ---------------- edge aggregation: one warp per destination node ----------------
// k,q,rel fp32 ; v gathered as bf16 pair-words (uint4 per lane). Pipelined depth-2.
__global__ void edge_agg_kernel(const float* __restrict__ rel,
                                const int* __restrict__ edge_feat,
                                const int* __restrict__ src)
{
    int gw = (blockIdx.x * blockDim.x + threadIdx.x) >> 5;
    int lane = threadIdx.x & 31;
    if (gw >= N_NODES) return;

    const float4* qr = (const float4*)(g_q + (size_t)gw * HS);
    float4 q0 = qr[2 * lane], q1 = qr[2 * lane + 1];

    float4 a0 = make_float4(0.f, 0.f, 0.f, 0.f);
    float4 a1 = make_float4(0.f, 0.f, 0.f, 0.f);
    float zsum = 0.f;

    const int beg = g_rowptr[gw], end = g_rowptr[gw + 1];
    const int ecol = 2 * (lane & 3);
    const float invs = 0.17677669529663687f;  // 1/sqrt(32)

    for (int base = beg; base < end; base += 32) {
        const int cnt = min(32, end - base);
        int s_l = 0, r_l = 0;
        if (base + lane < end) {
            int e = g_eids[base + lane];
            s_l = __ldg(&src[e]);
            r_l = __ldg(&edge_feat[e]);
        }

        int s_c = __shfl_sync(0xffffffffu, s_l, 0);
        int r_c = __shfl_sync(0xffffffffu, r_l, 0);
        const float4* kr = (const float4*)(g_k + (size_t)s_c * HS);
        const float4* er = (const float4*)(rel + (size_t)r_c * DK);
        float4 k0 = kr[2 * lane], k1 = kr[2 * lane + 1];
        uint4  vw = *(const uint4*)(g_vbf + (size_t)s_c * (HS / 2) + 4 * lane);
        float4 e0 = er[ecol],     e1 = er[ecol + 1];

        for (int j = 0; j < cnt; j++) {
            float4 K0 = k0, K1 = k1, E0 = e0, E1 = e1;
            uint4  VW = vw;
            if (j + 1 < cnt) {
                int s_n = __shfl_sync(0xffffffffu, s_l, j + 1);
                int r_n = __shfl_sync(0xffffffffu, r_l, j + 1);
                const float4* krn = (const float4*)(g_k + (size_t)s_n * HS);
                const float4* ern = (const float4*)(rel + (size_t)r_n * DK);
                k0 = krn[2 * lane]; k1 = krn[2 * lane + 1];
                vw = *(const uint4*)(g_vbf + (size_t)s_n * (HS / 2) + 4 * lane);
                e0 = ern[ecol];     e1 = ern[ecol + 1];
            }

            float d = (K0.x + E0.x) * q0.x + (K0.y + E0.y) * q0.y
                    + (K0.z + E0.z) * q0.z + (K0.w + E0.w) * q0.w
                    + (K1.x + E1.x) * q1.x + (K1.y + E1.y) * q1.y
                    + (K1.z + E1.z) * q1.z + (K1.w + E1.w) * q1.w;
            d += __shfl_xor_sync(0xffffffffu, d, 1);
            d += __shfl_xor_sync(0xffffffffu, d, 2);
            float sc = __expf(fminf(fmaxf(d * invs, -10.f), 10.f));

            float2 p0 = unpackbf2(VW.x), p1 = unpackbf2(VW.y);
            float2 p2 = unpackbf2(VW.z), p3 = unpackbf2(VW.w);
            a0.x += (p0.x + E0.x) * sc; a0.y += (p0.y + E0.y) * sc;
            a0.z += (p1.x + E0.z) * sc; a0.w += (p1.y + E0.w) * sc;
            a1.x += (p2.x + E1.x) * sc; a1.y += (p2.y + E1.y) * sc;
            a1.z += (p3.x + E1.z) * sc; a1.w += (p3.y + E1.w) * sc;
            zsum += sc;
        }
    }

    float inv = 1.f / zsum;
    uint4 w;
    w.x = packbf2(a0.x * inv, a0.y * inv);
    w.y = packbf2(a0.z * inv, a0.w * inv);
    w.z = packbf2(a1.x * inv, a1.y * inv);
    w.w = packbf2(a1.z * inv, a1.w * inv);
    *(uint4*)(g_obf + (size_t)gw * (HS / 2) + 4 * lane) = w;
}

// ---------------- layernorm: one warp per row; optional bf16 dual-write ----------------
__global__ void ln_kernel(const float* __restrict__ in,
                          const float* __restrict__ gamma,
                          const float* __restrict__ beta,
                          float* __restrict__ out,
                          uint32_t* __restrict__ outbf)
{
    int gw = (blockIdx.x * blockDim.x + threadIdx.x) >> 5;
    int lane = threadIdx.x & 31;
    if (gw >= N_NODES) return;

    const float4* row = (const float4*)(in + (size_t)gw * HS);
    float4 x0 = row[2 * lane], x1 = row[2 * lane + 1];

    float s = x0.x + x0.y + x0.z + x0.w + x1.x + x1.y + x1.z + x1.w;
    #pragma unroll
    for (int off = 16; off; off >>= 1) s += __shfl_xor_sync(0xffffffffu, s, off);
    float mean = s * (1.f / HS);

    float d0 = x0.x - mean, d1 = x0.y - mean, d2 = x0.z - mean, d3 = x0.w - mean;
    float d4 = x1.x - mean, d5 = x1.y - mean, d6 = x1.z - mean, d7 = x1.w - mean;
    float ss = d0 * d0 + d1 * d1 + d2 * d2 + d3 * d3 + d4 * d4 + d5 * d5 + d6 * d6 + d7 * d7;
    #pragma unroll
    for (int off = 16; off; off >>= 1) ss += __shfl_xor_sync(0xffffffffu, ss, off);
    float rstd = rsqrtf(ss * (1.f / HS) + 1e-5f);

    const float4* gr = (const float4*)gamma;
    const float4* br = (const float4*)beta;
    float4 gg0 = gr[2 * lane], gg1 = gr[2 * lane + 1];
    float4 bb0 = br[2 * lane], bb1 = br[2 * lane + 1];

    float o0 = d0 * rstd * gg0.x + bb0.x;
    float o1 = d1 * rstd * gg0.y + bb0.y;
    float o2 = d2 * rstd * gg0.z + bb0.z;
    float o3 = d3 * rstd * gg0.w + bb0.w;
    float o4 = d4 * rstd * gg1.x + bb1.x;
    float o5 = d5 * rstd * gg1.y + bb1.y;
    float o6 = d6 * rstd * gg1.z + bb1.z;
    float o7 = d7 * rstd * gg1.w + bb1.w;

    float4* orow = (float4*)(out + (size_t)gw * HS);
    orow[2 * lane]     = make_float4(o0, o1, o2, o3);
    orow[2 * lane + 1] = make_float4(o4, o5, o6, o7);

    if (outbf) {
        uint4 w;
        w.x = packbf2(o0, o1); w.y = packbf2(o2, o3);
        w.z = packbf2(o4, o5); w.w = packbf2(o6, o7);
        *(uint4*)(outbf + (size_t)gw * (HS / 2) + 4 * lane) = w;
    }
}

// ---------------- host orchestration ----------------
extern "C" void kernel_launch(void* const* d_in, const int* in_sizes, int n_in,
                              void* d_out, int out_size)
{
    const float* x_in     = (const float*)d_in[0];
    const int*   edge_feat= (const int*)  d_in[1];
    const int*   src      = (const int*)  d_in[2];
    const int*   dst      = (const int*)  d_in[3];
    const float* rel      = (const float*)d_in[4];
    const float* Wq       = (const float*)d_in[5];
    const float* bq       = (const float*)d_in[6];
    const float* Wk       = (const float*)d_in[7];
    const float* Wv       = (const float*)d_in[8];
    const float* Wo       = (const float*)d_in[9];
    const float* bo       = (const float*)d_in[10];
    const float* W1       = (const float*)d_in[11];
    const float* b1       = (const float*)d_in[12];
    const float* W2       = (const float*)d_in[13];
    const float* b2       = (const float*)d_in[14];
    const float* ln1g     = (const float*)d_in[15];
    const float* ln1b     = (const float*)d_in[16];
    const float* ln2g     = (const float*)d_in[17];
    const float* ln2b     = (const float*)d_in[18];

    float *q, *k, *tmp, *h, *xbuf;
    uint32_t *xbf, *vbf, *obf, *hbf, *ffbf, *wbf;
    int* cnt;
    cudaGetSymbolAddress((void**)&q,    g_q);
    cudaGetSymbolAddress((void**)&k,    g_k);
    cudaGetSymbolAddress((void**)&tmp,  g_tmp);
    cudaGetSymbolAddress((void**)&h,    g_h);
    cudaGetSymbolAddress((void**)&xbuf, g_xbuf);
    cudaGetSymbolAddress((void**)&xbf,  g_xbf);
    cudaGetSymbolAddress((void**)&vbf,  g_vbf);
    cudaGetSymbolAddress((void**)&obf,  g_obf);
    cudaGetSymbolAddress((void**)&hbf,  g_hbf);
    cudaGetSymbolAddress((void**)&ffbf, g_ffbf);
    cudaGetSymbolAddress((void**)&wbf,  g_wbf);
    cudaGetSymbolAddress((void**)&cnt,  g_cnt);

    convert_weights_kernel<<<(2 * WL_STRIDE + 255) / 256, 256>>>(Wq, Wk, Wv, Wo, W1, W2);
    convert_x_kernel<<<(N_NODES * HS / 2 + 255) / 256, 256>>>(x_in);

    cudaMemsetAsync(cnt, 0, N_NODES * sizeof(int));
    hist_kernel<<<(N_EDGES + 255) / 256, 256>>>(dst);
    scan_kernel<<<1, 1024>>>();
    scatter_kernel<<<(N_EDGES + 255) / 256, 256>>>(dst);

    const int warp_blocks = (N_NODES * 32 + 255) / 256;
    const int GM = (N_NODES + BM - 1) / BM;   // 157
    const int gnHS = HS / BN;                  // 2
    const int gnFF = FF_DIM / BN;              // 8
    const int tilesHS = GM * gnHS;             // 314
    const int tilesFF = GM * gnFF;             // 1256
    const int PGRID = 296;

    const float* xres = x_in;
    for (int l = 0; l < N_LAYERS; l++) {
        const uint32_t* wl = wbf + (size_t)l * WL_STRIDE;

        bf16_gemm_qkv_kernel<<<PGRID, 256>>>(N_NODES, HS, HS, gnHS, tilesHS,
                                             xbf, wl + WQ_OFF, wl + WK_OFF, wl + WV_OFF,
                                             bq + l * HS, q, k, vbf);

        edge_agg_kernel<<<warp_blocks, 256>>>(rel, edge_feat, src);

        bf16_gemm_kernel<2, false><<<PGRID, 256>>>(N_NODES, HS, HS, gnHS, tilesHS,
                                                   obf, wl + WO_OFF, bo + l * HS, xres, tmp, nullptr);
        ln_kernel<<<warp_blocks, 256>>>(tmp, ln1g + l * HS, ln1b + l * HS, h, hbf);

        bf16_gemm_kernel<1, true><<<PGRID, 256>>>(N_NODES, HS, FF_DIM, gnFF, tilesFF,
                                                  hbf, wl + W1_OFF, b1 + l * FF_DIM, nullptr, nullptr, ffbf);
        bf16_gemm_kernel<2, false><<<PGRID, 256>>>(N_NODES, FF_DIM, HS, gnHS, tilesHS,
                                                   ffbf, wl + W2_OFF, b2 + l * HS, h, tmp, nullptr);

        if (l == N_LAYERS - 1) {
            ln_kernel<<<warp_blocks, 256>>>(tmp, ln2g + l * HS, ln2b + l * HS, (float*)d_out, nullptr);
        } else {
            ln_kernel<<<warp_blocks, 256>>>(tmp, ln2g + l * HS, ln2b + l * HS, xbuf, xbf);
            xres = xbuf;
        }
    }
}

// round 12
// speedup vs baseline: 3.9488x; 1.0508x over previous
#include <cuda_runtime.h>
#include <cuda_bf16.h>
#include <cstdint>

#define N_NODES 20000
#define N_EDGES 640000
#define HS 256
#define H_HEADS 8
#define DK 32
#define FF_DIM 1024
#define N_LAYERS 2

// ---------------- scratch (static device globals; no runtime alloc) ----------------
__device__ float g_q[(size_t)N_NODES * HS];
__device__ float g_k[(size_t)N_NODES * HS];
__device__ float g_tmp[(size_t)N_NODES * HS];
__device__ float g_h[(size_t)N_NODES * HS];
__device__ float g_xbuf[(size_t)N_NODES * HS];

// bf16 pair-word activation buffers: word i = {val[2i], val[2i+1]} (row-major bf16)
__device__ __align__(16) uint32_t g_xbf[(size_t)N_NODES * HS / 2];
__device__ __align__(16) uint32_t g_vbf[(size_t)N_NODES * HS / 2];
__device__ __align__(16) uint32_t g_obf[(size_t)N_NODES * HS / 2];
__device__ __align__(16) uint32_t g_hbf[(size_t)N_NODES * HS / 2];
__device__ __align__(16) uint32_t g_ffbf[(size_t)N_NODES * FF_DIM / 2];

// k-major bf16 weights: word(k, n2) = {W[k][2*n2], W[k][2*n2+1]} at [k * Nc/2 + n2]
#define WQ_OFF 0
#define WK_OFF 32768
#define WV_OFF 65536
#define WO_OFF 98304
#define W1_OFF 131072
#define W2_OFF 262144
#define WL_STRIDE 393216
__device__ __align__(16) uint32_t g_wbf[2 * WL_STRIDE];

__device__ int g_cnt[N_NODES];
__device__ int g_rowptr[N_NODES + 1];
__device__ int g_cursor[N_NODES];
__device__ int g_eids[N_EDGES];

__device__ __forceinline__ uint32_t packbf2(float lo, float hi) {
    __nv_bfloat162 h = __float22bfloat162_rn(make_float2(lo, hi));
    return *reinterpret_cast<uint32_t*>(&h);
}

__device__ __forceinline__ float2 unpackbf2(uint32_t w) {
    return __bfloat1622float2(*reinterpret_cast<__nv_bfloat162*>(&w));
}

// ---------------- operand conversion ----------------
// k-major: output word w -> (matrix, k, n2); reads 2 consecutive floats (coalesced), writes coalesced.
__global__ void convert_weights_kernel(const float* __restrict__ Wq, const float* __restrict__ Wk,
                                       const float* __restrict__ Wv, const float* __restrict__ Wo,
                                       const float* __restrict__ W1, const float* __restrict__ W2) {
    int w = blockIdx.x * blockDim.x + threadIdx.x;
    if (w >= 2 * WL_STRIDE) return;
    int layer = w / WL_STRIDE;
    int r = w % WL_STRIDE;
    const float* src;
    int kk, n2, Nc;
    if (r < W1_OFF) {
        int m = r >> 15; int rr = r & 32767; Nc = HS;
        kk = rr >> 7; n2 = rr & 127;
        src = (m == 0 ? Wq : m == 1 ? Wk : m == 2 ? Wv : Wo) + (size_t)layer * HS * HS;
    } else if (r < W2_OFF) {
        int rr = r - W1_OFF; Nc = FF_DIM;
        kk = rr >> 9; n2 = rr & 511;
        src = W1 + (size_t)layer * HS * FF_DIM;
    } else {
        int rr = r - W2_OFF; Nc = HS;
        kk = rr >> 7; n2 = rr & 127;
        src = W2 + (size_t)layer * FF_DIM * HS;
    }
    const float* p = src + (size_t)kk * Nc + 2 * n2;
    g_wbf[w] = packbf2(p[0], p[1]);
}

__global__ void convert_x_kernel(const float* __restrict__ x) {
    int i = blockIdx.x * blockDim.x + threadIdx.x;
    if (i < N_NODES * HS / 2) g_xbf[i] = packbf2(x[2 * i], x[2 * i + 1]);
}

// ---------------- CSR build ----------------
__global__ void hist_kernel(const int* __restrict__ dst) {
    int i = blockIdx.x * blockDim.x + threadIdx.x;
    if (i < N_EDGES) atomicAdd(&g_cnt[dst[i]], 1);
}

__global__ void scan_kernel() {
    __shared__ int wsum[32];
    __shared__ int woff[32];
    __shared__ int total_sh;
    __shared__ int carry;
    const int tid = threadIdx.x, lane = tid & 31, wid = tid >> 5;
    if (tid == 0) carry = 0;
    __syncthreads();
    for (int base = 0; base < N_NODES; base += 1024) {
        int i = base + tid;
        int v = (i < N_NODES) ? g_cnt[i] : 0;
        int incl = v;
        #pragma unroll
        for (int off = 1; off < 32; off <<= 1) {
            int t = __shfl_up_sync(0xffffffffu, incl, off);
            if (lane >= off) incl += t;
        }
        if (lane == 31) wsum[wid] = incl;
        __syncthreads();
        if (wid == 0) {
            int s = wsum[lane];
            int si = s;
            #pragma unroll
            for (int off = 1; off < 32; off <<= 1) {
                int t = __shfl_up_sync(0xffffffffu, si, off);
                if (lane >= off) si += t;
            }
            woff[lane] = si - s;
            if (lane == 31) total_sh = si;
        }
        __syncthreads();
        int excl = incl - v + woff[wid] + carry;
        if (i < N_NODES) {
            g_rowptr[i] = excl;
            g_cursor[i] = excl;
        }
        __syncthreads();
        if (tid == 0) carry += total_sh;
    }
    if (tid == 0) g_rowptr[N_NODES] = carry;
}

__global__ void scatter_kernel(const int* __restrict__ dst) {
    int i = blockIdx.x * blockDim.x + threadIdx.x;
    if (i < N_EDGES) {
        int p = atomicAdd(&g_cursor[dst[i]], 1);
        g_eids[p] = i;
    }
}

// ---------------- BF16 TC GEMM: cp.async + ldmatrix, persistent CTAs ----------------
// A: row-major bf16 (pair-words [m][K/2]) ; B: k-major bf16 (pair-words [k][Nc/2]).
// Chunk = 64 k. A smem: 128 rows x 128B; B smem: 64 k-rows x 256B. XOR-(row&7) 16B-group swizzle.
// MODE 0: +bias (nullable)   MODE 1: relu(+bias)   MODE 2: +bias +res
#define BM 128
#define BN 128
#define GEMM_SMEM_BYTES 65536   // [A0|A1|B0|B1] x 16KB

__device__ __forceinline__ void cp_async16(uint32_t dst, const void* src, uint32_t sz) {
    asm volatile("cp.async.ca.shared.global [%0], [%1], 16, %2;"
                 :: "r"(dst), "l"(src), "r"(sz) : "memory");
}
__device__ __forceinline__ void cp_commit() {
    asm volatile("cp.async.commit_group;" ::: "memory");
}
__device__ __forceinline__ void cp_wait1() {
    asm volatile("cp.async.wait_group 1;" ::: "memory");
}
__device__ __forceinline__ void cp_wait0() {
    asm volatile("cp.async.wait_group 0;" ::: "memory");
}

__device__ __forceinline__ uint32_t smem_u32(const void* p) {
    uint32_t a;
    asm("{ .reg .u64 t; cvta.to.shared.u64 t, %1; cvt.u32.u64 %0, t; }" : "=r"(a) : "l"(p));
    return a;
}

#define LDMX4(r0, r1, r2, r3, addr) \
    asm volatile("ldmatrix.sync.aligned.m8n8.x4.shared.b16 {%0,%1,%2,%3}, [%4];" \
                 : "=r"(r0), "=r"(r1), "=r"(r2), "=r"(r3) : "r"(addr))

#define LDMX4T(r0, r1, r2, r3, addr) \
    asm volatile("ldmatrix.sync.aligned.m8n8.x4.trans.shared.b16 {%0,%1,%2,%3}, [%4];" \
                 : "=r"(r0), "=r"(r1), "=r"(r2), "=r"(r3) : "r"(addr))

__device__ __forceinline__ void mma_bf16(float4& c, const uint32_t a[4], const uint32_t b[2]) {
    asm volatile(
        "mma.sync.aligned.m16n8k16.row.col.f32.bf16.bf16.f32 "
        "{%0,%1,%2,%3}, {%4,%5,%6,%7}, {%8,%9}, {%0,%1,%2,%3};"
        : "+f"(c.x), "+f"(c.y), "+f"(c.z), "+f"(c.w)
        : "r"(a[0]), "r"(a[1]), "r"(a[2]), "r"(a[3]), "r"(b[0]), "r"(b[1]));
}

template <int MODE, bool OUTBF>
__device__ __forceinline__ void gemm_tile(
    uint32_t sbase,                        // smem byte base (cvta'd, 1KB aligned)
    int M, int K, int Nc, int m0, int n0,
    const uint32_t* __restrict__ Aw,       // [m][K/2]
    const uint32_t* __restrict__ Bw,       // [k][Nc/2]
    const float* __restrict__ bias,
    const float* __restrict__ res,
    float* __restrict__ C,
    uint32_t* __restrict__ Cbf)
{
    const int tid  = threadIdx.x;
    const int lane = tid & 31;
    const int warp = tid >> 5;
    const int g  = lane >> 2;
    const int tg = lane & 3;
    const int wm = (warp >> 2) * 64;
    const int wn = (warp & 3) * 32;

    const int Khalf = K >> 1;
    const int Nhalf = Nc >> 1;
    const int nch = K >> 6;                // 64-k chunks

    // ---- fill thread mapping ----
    const int fa_row = tid >> 1;           // 0..127
    const int fa_h0  = (tid & 1) * 4;      // group base 0/4
    const int fb_row = tid >> 2;           // 0..63 (k row within chunk)
    const int fb_h0  = (tid & 3) * 4;      // group base 0..12

    const int arow_g   = m0 + fa_row;
    const uint32_t asz = (arow_g < M) ? 16u : 0u;
    const uint32_t* aSrcRow = Aw + (size_t)((arow_g < M) ? arow_g : (M - 1)) * Khalf + fa_h0 * 4;
    const uint32_t aDst0 = sbase + fa_row * 128;
    const uint32_t* bSrcRow0 = Bw + (size_t)fb_row * Nhalf + (n0 >> 1) + fb_h0 * 4;
    const uint32_t bDst0 = sbase + 32768 + fb_row * 256;

    // ---- ldmatrix addresses (h=0 / ks=0), lane-static ----
    const int lr = lane & 7;
    const int mi = lane >> 3;
    const int hs = lane >> 4;              // 0/1 : k-half select for A
    uint32_t aAddr0[4];
    #pragma unroll
    for (int mt = 0; mt < 4; mt++) {
        int r = wm + mt * 16 + lr + (mi & 1) * 8;
        aAddr0[mt] = sbase + r * 128 + ((r & 7) << 4);
    }
    uint32_t bAddr0[2];
    #pragma unroll
    for (int np = 0; np < 2; np++) {
        int kR = (mi >> 1) * 8 + lr;                   // k row within k16
        int hB = (wn >> 3) + np * 2 + (mi & 1);        // n-group
        bAddr0[np] = sbase + 32768 + kR * 256 + ((hB ^ lr) << 4);
    }

    float4 acc[4][4];
    #pragma unroll
    for (int i = 0; i < 4; i++)
        #pragma unroll
        for (int j = 0; j < 4; j++) acc[i][j] = make_float4(0.f, 0.f, 0.f, 0.f);

    // ---- prologue: chunk 0 -> buffer 0 ----
    {
        #pragma unroll
        for (int j = 0; j < 4; j++) {
            int h = fa_h0 + j;
            cp_async16(aDst0 + ((h ^ (fa_row & 7)) << 4), aSrcRow + j * 4, asz);
        }
        #pragma unroll
        for (int j = 0; j < 4; j++) {
            int h = fb_h0 + j;
            cp_async16(bDst0 + ((h ^ (fb_row & 7)) << 4), bSrcRow0 + j * 4, 16u);
        }
        cp_commit();
    }

    for (int ch = 0; ch < nch; ch++) {
        const uint32_t abuf = (ch & 1) ? 16384u : 0u;
        const uint32_t bbuf = abuf;
        const bool has_next = (ch + 1 < nch);

        if (has_next) {
            const uint32_t nbuf = 16384u - abuf;
            const int kw0 = (ch + 1) * 32;             // A words
            #pragma unroll
            for (int j = 0; j < 4; j++) {
                int h = fa_h0 + j;
                cp_async16(aDst0 + nbuf + ((h ^ (fa_row & 7)) << 4), aSrcRow + kw0 + j * 4, asz);
            }
            const size_t bk = (size_t)(ch + 1) * 64 * Nhalf;  // B k-row advance
            #pragma unroll
            for (int j = 0; j < 4; j++) {
                int h = fb_h0 + j;
                cp_async16(bDst0 + nbuf + ((h ^ (fb_row & 7)) << 4), bSrcRow0 + bk + j * 4, 16u);
            }
            cp_commit();
            cp_wait1();
        } else {
            cp_wait0();
        }
        __syncthreads();

        #pragma unroll
        for (int ks = 0; ks < 4; ks++) {
            uint32_t afr[4][4];
            uint32_t bfr[4][2];
            const uint32_t hxor = (uint32_t)((2 * ks + hs) << 4);
            #pragma unroll
            for (int mt = 0; mt < 4; mt++)
                LDMX4(afr[mt][0], afr[mt][1], afr[mt][2], afr[mt][3],
                      (aAddr0[mt] + abuf) ^ hxor);
            #pragma unroll
            for (int np = 0; np < 2; np++) {
                uint32_t r0, r1, r2, r3;
                LDMX4T(r0, r1, r2, r3, bAddr0[np] + bbuf + ks * 4096);
                bfr[2 * np][0] = r0; bfr[2 * np][1] = r2;
                bfr[2 * np + 1][0] = r1; bfr[2 * np + 1][1] = r3;
            }
            #pragma unroll
            for (int mt = 0; mt < 4; mt++)
                #pragma unroll
                for (int nt = 0; nt < 4; nt++)
                    mma_bf16(acc[mt][nt], afr[mt], bfr[nt]);
        }
        __syncthreads();
    }

    // ---- epilogue ----
    #pragma unroll
    for (int mt = 0; mt < 4; mt++) {
        #pragma unroll
        for (int nt = 0; nt < 4; nt++) {
            const int row0 = m0 + wm + mt * 16 + g;
            const int row1 = row0 + 8;
            const int col  = n0 + wn + nt * 8 + tg * 2;
            float2 v0 = make_float2(acc[mt][nt].x, acc[mt][nt].y);
            float2 v1 = make_float2(acc[mt][nt].z, acc[mt][nt].w);
            if (bias) {
                float2 bb = *(const float2*)(bias + col);
                v0.x += bb.x; v0.y += bb.y;
                v1.x += bb.x; v1.y += bb.y;
            }
            if (MODE == 2) {
                if (row0 < M) {
                    float2 r0 = *(const float2*)(res + (size_t)row0 * Nc + col);
                    v0.x += r0.x; v0.y += r0.y;
                }
                if (row1 < M) {
                    float2 r1 = *(const float2*)(res + (size_t)row1 * Nc + col);
                    v1.x += r1.x; v1.y += r1.y;
                }
            }
            if (MODE == 1) {
                v0.x = fmaxf(v0.x, 0.f); v0.y = fmaxf(v0.y, 0.f);
                v1.x = fmaxf(v1.x, 0.f); v1.y = fmaxf(v1.y, 0.f);
            }
            if (OUTBF) {
                if (row0 < M) Cbf[(size_t)row0 * (Nc >> 1) + (col >> 1)] = packbf2(v0.x, v0.y);
                if (row1 < M) Cbf[(size_t)row1 * (Nc >> 1) + (col >> 1)] = packbf2(v1.x, v1.y);
            } else {
                if (row0 < M) *(float2*)(C + (size_t)row0 * Nc + col) = v0;
                if (row1 < M) *(float2*)(C + (size_t)row1 * Nc + col) = v1;
            }
        }
    }
}

template <int MODE, bool OUTBF>
__global__ __launch_bounds__(256, 2) void bf16_gemm_kernel(
    int M, int K, int Nc, int gn, int total_tiles,
    const uint32_t* __restrict__ Aw,
    const uint32_t* __restrict__ Bw,
    const float* __restrict__ bias,
    const float* __restrict__ res,
    float* __restrict__ C,
    uint32_t* __restrict__ Cbf)
{
    extern __shared__ __align__(1024) uint32_t dynsmem[];
    const uint32_t sbase = smem_u32(dynsmem);
    for (int t = blockIdx.x; t < total_tiles; t += gridDim.x) {
        const int m0 = (t / gn) * BM;
        const int n0 = (t % gn) * BN;
        gemm_tile<MODE, OUTBF>(sbase, M, K, Nc, m0, n0, Aw, Bw, bias, res, C, Cbf);
    }
}

// fused q/k/v: q,k -> fp32 ; v -> bf16 pair-words
__global__ __launch_bounds__(256, 2) void bf16_gemm_qkv_kernel(
    int M, int K, int Nc, int gn, int tiles_per,
    const uint32_t* __restrict__ Aw,
    const uint32_t* __restrict__ Bq,
    const uint32_t* __restrict__ Bk,
    const uint32_t* __restrict__ Bv,
    const float* __restrict__ biasq,
    float* __restrict__ Cq,
    float* __restrict__ Ck,
    uint32_t* __restrict__ Cvbf)
{
    extern __shared__ __align__(1024) uint32_t dynsmem[];
    const uint32_t sbase = smem_u32(dynsmem);
    const int total = 3 * tiles_per;
    for (int t = blockIdx.x; t < total; t += gridDim.x) {
        const int which = t / tiles_per;
        const int tt = t % tiles_per;
        const int m0 = (tt / gn) * BM;
        const int n0 = (tt % gn) * BN;
        if (which == 2) {
            gemm_tile<0, true>(sbase, M, K, Nc, m0, n0, Aw, Bv, nullptr, nullptr, nullptr, Cvbf);
        } else {
            const uint32_t* B = (which == 0) ? Bq : Bk;
            float* C          = (which == 0) ? Cq : Ck;
            const float* bias = (which == 0) ? biasq : nullptr;
            gemm_tile<0, false>(sbase, M, K, Nc, m0, n0, Aw, B, bias, nullptr, C, nullptr);
        }
    }
}

// ---------------- edge aggregation: one warp per destination node ----------------
__global__ void edge_agg_kernel(const float* __restrict__ rel,
                                const int* __restrict__ edge_feat,
                                const int* __restrict__ src)
{
    int gw = (blockIdx.x * blockDim.x + threadIdx.x) >> 5;
    int lane = threadIdx.x & 31;
    if (gw >= N_NODES) return;

    const float4* qr = (const float4*)(g_q + (size_t)gw * HS);
    float4 q0 = qr[2 * lane], q1 = qr[2 * lane + 1];

    float4 a0 = make_float4(0.f, 0.f, 0.f, 0.f);
    float4 a1 = make_float4(0.f, 0.f, 0.f, 0.f);
    float zsum = 0.f;

    const int beg = g_rowptr[gw], end = g_rowptr[gw + 1];
    const int ecol = 2 * (lane & 3);
    const float invs = 0.17677669529663687f;  // 1/sqrt(32)

    for (int base = beg; base < end; base += 32) {
        const int cnt = min(32, end - base);
        int s_l = 0, r_l = 0;
        if (base + lane < end) {
            int e = g_eids[base + lane];
            s_l = __ldg(&src[e]);
            r_l = __ldg(&edge_feat[e]);
        }

        int s_c = __shfl_sync(0xffffffffu, s_l, 0);
        int r_c = __shfl_sync(0xffffffffu, r_l, 0);
        const float4* kr = (const float4*)(g_k + (size_t)s_c * HS);
        const float4* er = (const float4*)(rel + (size_t)r_c * DK);
        float4 k0 = kr[2 * lane], k1 = kr[2 * lane + 1];
        uint4  vw = *(const uint4*)(g_vbf + (size_t)s_c * (HS / 2) + 4 * lane);
        float4 e0 = er[ecol],     e1 = er[ecol + 1];

        for (int j = 0; j < cnt; j++) {
            float4 K0 = k0, K1 = k1, E0 = e0, E1 = e1;
            uint4  VW = vw;
            if (j + 1 < cnt) {
                int s_n = __shfl_sync(0xffffffffu, s_l, j + 1);
                int r_n = __shfl_sync(0xffffffffu, r_l, j + 1);
                const float4* krn = (const float4*)(g_k + (size_t)s_n * HS);
                const float4* ern = (const float4*)(rel + (size_t)r_n * DK);
                k0 = krn[2 * lane]; k1 = krn[2 * lane + 1];
                vw = *(const uint4*)(g_vbf + (size_t)s_n * (HS / 2) + 4 * lane);
                e0 = ern[ecol];     e1 = ern[ecol + 1];
            }

            float d = (K0.x + E0.x) * q0.x + (K0.y + E0.y) * q0.y
                    + (K0.z + E0.z) * q0.z + (K0.w + E0.w) * q0.w
                    + (K1.x + E1.x) * q1.x + (K1.y + E1.y) * q1.y
                    + (K1.z + E1.z) * q1.z + (K1.w + E1.w) * q1.w;
            d += __shfl_xor_sync(0xffffffffu, d, 1);
            d += __shfl_xor_sync(0xffffffffu, d, 2);
            float sc = __expf(fminf(fmaxf(d * invs, -10.f), 10.f));

            float2 p0 = unpackbf2(VW.x), p1 = unpackbf2(VW.y);
            float2 p2 = unpackbf2(VW.z), p3 = unpackbf2(VW.w);
            a0.x += (p0.x + E0.x) * sc; a0.y += (p0.y + E0.y) * sc;
            a0.z += (p1.x + E0.z) * sc; a0.w += (p1.y + E0.w) * sc;
            a1.x += (p2.x + E1.x) * sc; a1.y += (p2.y + E1.y) * sc;
            a1.z += (p3.x + E1.z) * sc; a1.w += (p3.y + E1.w) * sc;
            zsum += sc;
        }
    }

    float inv = 1.f / zsum;
    uint4 w;
    w.x = packbf2(a0.x * inv, a0.y * inv);
    w.y = packbf2(a0.z * inv, a0.w * inv);
    w.z = packbf2(a1.x * inv, a1.y * inv);
    w.w = packbf2(a1.z * inv, a1.w * inv);
    *(uint4*)(g_obf + (size_t)gw * (HS / 2) + 4 * lane) = w;
}

// ---------------- layernorm: one warp per row; optional bf16 dual-write ----------------
__global__ void ln_kernel(const float* __restrict__ in,
                          const float* __restrict__ gamma,
                          const float* __restrict__ beta,
                          float* __restrict__ out,
                          uint32_t* __restrict__ outbf)
{
    int gw = (blockIdx.x * blockDim.x + threadIdx.x) >> 5;
    int lane = threadIdx.x & 31;
    if (gw >= N_NODES) return;

    const float4* row = (const float4*)(in + (size_t)gw * HS);
    float4 x0 = row[2 * lane], x1 = row[2 * lane + 1];

    float s = x0.x + x0.y + x0.z + x0.w + x1.x + x1.y + x1.z + x1.w;
    #pragma unroll
    for (int off = 16; off; off >>= 1) s += __shfl_xor_sync(0xffffffffu, s, off);
    float mean = s * (1.f / HS);

    float d0 = x0.x - mean, d1 = x0.y - mean, d2 = x0.z - mean, d3 = x0.w - mean;
    float d4 = x1.x - mean, d5 = x1.y - mean, d6 = x1.z - mean, d7 = x1.w - mean;
    float ss = d0 * d0 + d1 * d1 + d2 * d2 + d3 * d3 + d4 * d4 + d5 * d5 + d6 * d6 + d7 * d7;
    #pragma unroll
    for (int off = 16; off; off >>= 1) ss += __shfl_xor_sync(0xffffffffu, ss, off);
    float rstd = rsqrtf(ss * (1.f / HS) + 1e-5f);

    const float4* gr = (const float4*)gamma;
    const float4* br = (const float4*)beta;
    float4 gg0 = gr[2 * lane], gg1 = gr[2 * lane + 1];
    float4 bb0 = br[2 * lane], bb1 = br[2 * lane + 1];

    float o0 = d0 * rstd * gg0.x + bb0.x;
    float o1 = d1 * rstd * gg0.y + bb0.y;
    float o2 = d2 * rstd * gg0.z + bb0.z;
    float o3 = d3 * rstd * gg0.w + bb0.w;
    float o4 = d4 * rstd * gg1.x + bb1.x;
    float o5 = d5 * rstd * gg1.y + bb1.y;
    float o6 = d6 * rstd * gg1.z + bb1.z;
    float o7 = d7 * rstd * gg1.w + bb1.w;

    float4* orow = (float4*)(out + (size_t)gw * HS);
    orow[2 * lane]     = make_float4(o0, o1, o2, o3);
    orow[2 * lane + 1] = make_float4(o4, o5, o6, o7);

    if (outbf) {
        uint4 w;
        w.x = packbf2(o0, o1); w.y = packbf2(o2, o3);
        w.z = packbf2(o4, o5); w.w = packbf2(o6, o7);
        *(uint4*)(outbf + (size_t)gw * (HS / 2) + 4 * lane) = w;
    }
}

// ---------------- host orchestration ----------------
extern "C" void kernel_launch(void* const* d_in, const int* in_sizes, int n_in,
                              void* d_out, int out_size)
{
    const float* x_in     = (const float*)d_in[0];
    const int*   edge_feat= (const int*)  d_in[1];
    const int*   src      = (const int*)  d_in[2];
    const int*   dst      = (const int*)  d_in[3];
    const float* rel      = (const float*)d_in[4];
    const float* Wq       = (const float*)d_in[5];
    const float* bq       = (const float*)d_in[6];
    const float* Wk       = (const float*)d_in[7];
    const float* Wv       = (const float*)d_in[8];
    const float* Wo       = (const float*)d_in[9];
    const float* bo       = (const float*)d_in[10];
    const float* W1       = (const float*)d_in[11];
    const float* b1       = (const float*)d_in[12];
    const float* W2       = (const float*)d_in[13];
    const float* b2       = (const float*)d_in[14];
    const float* ln1g     = (const float*)d_in[15];
    const float* ln1b     = (const float*)d_in[16];
    const float* ln2g     = (const float*)d_in[17];
    const float* ln2b     = (const float*)d_in[18];

    float *q, *k, *tmp, *h, *xbuf;
    uint32_t *xbf, *vbf, *obf, *hbf, *ffbf, *wbf;
    int* cnt;
    cudaGetSymbolAddress((void**)&q,    g_q);
    cudaGetSymbolAddress((void**)&k,    g_k);
    cudaGetSymbolAddress((void**)&tmp,  g_tmp);
    cudaGetSymbolAddress((void**)&h,    g_h);
    cudaGetSymbolAddress((void**)&xbuf, g_xbuf);
    cudaGetSymbolAddress((void**)&xbf,  g_xbf);
    cudaGetSymbolAddress((void**)&vbf,  g_vbf);
    cudaGetSymbolAddress((void**)&obf,  g_obf);
    cudaGetSymbolAddress((void**)&hbf,  g_hbf);
    cudaGetSymbolAddress((void**)&ffbf, g_ffbf);
    cudaGetSymbolAddress((void**)&wbf,  g_wbf);
    cudaGetSymbolAddress((void**)&cnt,  g_cnt);

    // opt-in to 64KB dynamic smem (idempotent; not a stream op)
    cudaFuncSetAttribute(bf16_gemm_qkv_kernel,
                         cudaFuncAttributeMaxDynamicSharedMemorySize, GEMM_SMEM_BYTES);
    cudaFuncSetAttribute(bf16_gemm_kernel<2, false>,
                         cudaFuncAttributeMaxDynamicSharedMemorySize, GEMM_SMEM_BYTES);
    cudaFuncSetAttribute(bf16_gemm_kernel<1, true>,
                         cudaFuncAttributeMaxDynamicSharedMemorySize, GEMM_SMEM_BYTES);

    convert_weights_kernel<<<(2 * WL_STRIDE + 255) / 256, 256>>>(Wq, Wk, Wv, Wo, W1, W2);
    convert_x_kernel<<<(N_NODES * HS / 2 + 255) / 256, 256>>>(x_in);

    cudaMemsetAsync(cnt, 0, N_NODES * sizeof(int));
    hist_kernel<<<(N_EDGES + 255) / 256, 256>>>(dst);
    scan_kernel<<<1, 1024>>>();
    scatter_kernel<<<(N_EDGES + 255) / 256, 256>>>(dst);

    const int warp_blocks = (N_NODES * 32 + 255) / 256;
    const int GM = (N_NODES + BM - 1) / BM;   // 157
    const int gnHS = HS / BN;                  // 2
    const int gnFF = FF_DIM / BN;              // 8
    const int tilesHS = GM * gnHS;             // 314
    const int tilesFF = GM * gnFF;             // 1256
    const int PGRID = 296;

    const float* xres = x_in;
    for (int l = 0; l < N_LAYERS; l++) {
        const uint32_t* wl = wbf + (size_t)l * WL_STRIDE;

        bf16_gemm_qkv_kernel<<<PGRID, 256, GEMM_SMEM_BYTES>>>(
            N_NODES, HS, HS, gnHS, tilesHS,
            xbf, wl + WQ_OFF, wl + WK_OFF, wl + WV_OFF,
            bq + l * HS, q, k, vbf);

        edge_agg_kernel<<<warp_blocks, 256>>>(rel, edge_feat, src);

        bf16_gemm_kernel<2, false><<<PGRID, 256, GEMM_SMEM_BYTES>>>(
            N_NODES, HS, HS, gnHS, tilesHS,
            obf, wl + WO_OFF, bo + l * HS, xres, tmp, nullptr);
        ln_kernel<<<warp_blocks, 256>>>(tmp, ln1g + l * HS, ln1b + l * HS, h, hbf);

        bf16_gemm_kernel<1, true><<<PGRID, 256, GEMM_SMEM_BYTES>>>(
            N_NODES, HS, FF_DIM, gnFF, tilesFF,
            hbf, wl + W1_OFF, b1 + l * FF_DIM, nullptr, nullptr, ffbf);
        bf16_gemm_kernel<2, false><<<PGRID, 256, GEMM_SMEM_BYTES>>>(
            N_NODES, FF_DIM, HS, gnHS, tilesHS,
            ffbf, wl + W2_OFF, b2 + l * HS, h, tmp, nullptr);

        if (l == N_LAYERS - 1) {
            ln_kernel<<<warp_blocks, 256>>>(tmp, ln2g + l * HS, ln2b + l * HS, (float*)d_out, nullptr);
        } else {
            ln_kernel<<<warp_blocks, 256>>>(tmp, ln2g + l * HS, ln2b + l * HS, xbuf, xbf);
            xres = xbuf;
        }
    }
}